// round 10
// baseline (speedup 1.0000x reference)
#include <cuda_runtime.h>
#include <cuda_bf16.h>
#include <cuda_fp16.h>

#define NN 100000
#define NE 6400000
#define EGRID 296
#define ETB 512
#define ETHREADS (EGRID * ETB)   // 151552 = 148 SMs x 2 blocks x 512
#define UGRID 296
#define UTB 256
#define UTHREADS (UGRID * UTB)   // 75776
static constexpr float BN_EPS = 1e-5f;

// ---------------- scratch (static device arrays; no runtime alloc) ---------
__device__ float4 g_A[NN];            // h @ msg_W1[0:4]   (dst-side partial)
__device__ float4 g_B[NN];            // h @ msg_W1[4:8]+b (src-side partial)
__device__ uint2  g_z16[NE];          // per-edge layer-1 pre-BN, packed half4 (51.2 MB)
__device__ float4 g_aggr[NN];         // scatter-add target

__device__ double g_sum[4];
__device__ double g_sq[4];

// generation-based grid barriers: monotonic, never reset (replay-safe)
__device__ unsigned long long          g_ebar_cnt;
__device__ volatile unsigned long long g_ebar_rel;
__device__ unsigned long long          g_ubar_cnt;
__device__ volatile unsigned long long g_ubar_rel;

__device__ float g_ma1[4], g_mb1[4];  // msg BN1 affine
__device__ float g_ma2[4], g_mb2[4];  // msg BN2 affine
__device__ float g_ua1[4], g_ub1[4];  // upd BN1 affine
__device__ float g_ua2[4], g_ub2[4];  // upd BN2 affine

struct P {
    const float* pos; const float* vel;
    const int* src; const int* dst;   // edge_index rows (int32)
    const float *mW1,*mb1,*mg1,*mbe1,*mW2,*mb2,*mg2,*mbe2;
    const float *uW1,*ub1,*ug1,*ube1,*uW2,*ub2,*ug2,*ube2;
    const float *pW,*pb;
    float* out;
};

// ---------------- half4 pack/unpack -----------------------------------------
__device__ __forceinline__ uint2 pack_half4(const float z[4]) {
    __half2 a = __floats2half2_rn(z[0], z[1]);
    __half2 b = __floats2half2_rn(z[2], z[3]);
    uint2 u;
    u.x = *reinterpret_cast<unsigned*>(&a);
    u.y = *reinterpret_cast<unsigned*>(&b);
    return u;
}
__device__ __forceinline__ void unpack_half4(unsigned lo, unsigned hi, float z[4]) {
    __half2 a = *reinterpret_cast<__half2*>(&lo);
    __half2 b = *reinterpret_cast<__half2*>(&hi);
    float2 f0 = __half22float2(a), f1 = __half22float2(b);
    z[0] = f0.x; z[1] = f0.y; z[2] = f1.x; z[3] = f1.y;
}

// ---------------- block-level stats reduce -> global atomics ----------------
// Supports up to 512-thread blocks (16 warps).
__device__ __forceinline__ void reduce_stats(float s[4], float q[4]) {
    #pragma unroll
    for (int o = 16; o > 0; o >>= 1) {
        #pragma unroll
        for (int c = 0; c < 4; c++) {
            s[c] += __shfl_down_sync(0xffffffffu, s[c], o);
            q[c] += __shfl_down_sync(0xffffffffu, q[c], o);
        }
    }
    __shared__ float shs[4][16], shq[4][16];
    int w = threadIdx.x >> 5;
    if ((threadIdx.x & 31) == 0) {
        #pragma unroll
        for (int c = 0; c < 4; c++) { shs[c][w] = s[c]; shq[c][w] = q[c]; }
    }
    __syncthreads();
    if (threadIdx.x == 0) {
        int nw = blockDim.x >> 5;
        #pragma unroll
        for (int c = 0; c < 4; c++) {
            double ts = 0.0, tq = 0.0;
            for (int i = 0; i < nw; i++) { ts += (double)shs[c][i]; tq += (double)shq[c][i]; }
            atomicAdd(&g_sum[c], ts);
            atomicAdd(&g_sq[c],  tq);
        }
    }
}

// finalize BN affine from global moments (VOLATILE reads: bypass stale L1)
__device__ __forceinline__ void bn_finalize(double count, const float* gamma, const float* beta,
                                            float* aout, float* bout) {
    #pragma unroll
    for (int c = 0; c < 4; c++) {
        double m = ((volatile double*)g_sum)[c] / count;
        double v = ((volatile double*)g_sq)[c] / count - m * m;
        float  al = __ldg(&gamma[c]) * rsqrtf((float)v + BN_EPS);
        aout[c] = al;
        bout[c] = __ldg(&beta[c]) - (float)m * al;
        g_sum[c] = 0.0; g_sq[c] = 0.0;
    }
}

// generation-based grid barrier; last arriver optionally runs BN finalize.
__device__ __forceinline__ void grid_barrier(unsigned long long* cnt,
                                             volatile unsigned long long* rel,
                                             int grid,
                                             double count = 0.0,
                                             const float* gamma = nullptr,
                                             const float* beta  = nullptr,
                                             float* aout = nullptr, float* bout = nullptr) {
    __threadfence();
    __syncthreads();
    if (threadIdx.x == 0) {
        unsigned long long old = atomicAdd(cnt, 1ULL);
        unsigned long long gen = old / (unsigned long long)grid;
        if (old % (unsigned long long)grid == (unsigned long long)(grid - 1)) {
            if (gamma) bn_finalize(count, gamma, beta, aout, bout);
            __threadfence();
            *rel = gen + 1;
        } else {
            while (*rel <= gen) __nanosleep(32);
        }
        __threadfence();
    }
    __syncthreads();
}

// ======================= edge kernel (phases 0-3) ===========================
// Cache policy: streaming traffic (indices, z buffer) uses .cg (L2-only) so
// L1 stays dedicated to the random A/B table gathers.
__global__ void __launch_bounds__(ETB, 2) k_edge(P p) {
    const int tid = blockIdx.x * ETB + threadIdx.x;

    // ---- phase 0: per-node precompute A,B + aggr reset ----
    if (tid < NN) {
        float h0 = __ldg(&p.pos[2*tid]),  h1 = __ldg(&p.pos[2*tid+1]);
        float h2 = __ldg(&p.vel[2*tid]),  h3 = __ldg(&p.vel[2*tid+1]);
        float A[4], B[4];
        #pragma unroll
        for (int c = 0; c < 4; c++) {
            A[c] = h0*__ldg(&p.mW1[ 0+c]) + h1*__ldg(&p.mW1[ 4+c])
                 + h2*__ldg(&p.mW1[ 8+c]) + h3*__ldg(&p.mW1[12+c]);
            B[c] = __ldg(&p.mb1[c])
                 + h0*__ldg(&p.mW1[16+c]) + h1*__ldg(&p.mW1[20+c])
                 + h2*__ldg(&p.mW1[24+c]) + h3*__ldg(&p.mW1[28+c]);
        }
        g_A[tid]    = make_float4(A[0], A[1], A[2], A[3]);
        g_B[tid]    = make_float4(B[0], B[1], B[2], B[3]);
        g_aggr[tid] = make_float4(0.f, 0.f, 0.f, 0.f);
    }
    grid_barrier(&g_ebar_cnt, &g_ebar_rel, EGRID);

    // ---- phase 1: gather once, pack-store z (.cg), BN1 stats (2 edges/iter) --
    {
        float s[4] = {0,0,0,0}, q[4] = {0,0,0,0};
        const int2* src2 = (const int2*)p.src;
        const int2* dst2 = (const int2*)p.dst;
        uint4* z4 = (uint4*)g_z16;
        for (int j = tid; j < NE/2; j += ETHREADS) {
            int2 si = __ldcg(&src2[j]);
            int2 di = __ldcg(&dst2[j]);
            float4 A0 = g_A[di.x], B0 = g_B[si.x];
            float4 A1 = g_A[di.y], B1 = g_B[si.y];
            float z0[4] = {A0.x+B0.x, A0.y+B0.y, A0.z+B0.z, A0.w+B0.w};
            float z1[4] = {A1.x+B1.x, A1.y+B1.y, A1.z+B1.z, A1.w+B1.w};
            uint2 u0 = pack_half4(z0);
            uint2 u1 = pack_half4(z1);
            __stcg(&z4[j], make_uint4(u0.x, u0.y, u1.x, u1.y));
            #pragma unroll
            for (int c = 0; c < 4; c++) {
                s[c] += z0[c] + z1[c];
                q[c] += z0[c]*z0[c] + z1[c]*z1[c];
            }
        }
        reduce_stats(s, q);
    }
    grid_barrier(&g_ebar_cnt, &g_ebar_rel, EGRID,
                 (double)NE, p.mg1, p.mbe1, g_ma1, g_mb1);

    // ---- phase 2: stream z (.cg), BN2 stats (2 edges/iter) ----
    {
        float a1[4], b1[4], W2[16], bb2[4];
        #pragma unroll
        for (int c = 0; c < 4; c++) { a1[c] = g_ma1[c]; b1[c] = g_mb1[c]; bb2[c] = __ldg(&p.mb2[c]); }
        #pragma unroll
        for (int k = 0; k < 16; k++) W2[k] = __ldg(&p.mW2[k]);

        float s[4] = {0,0,0,0}, q[4] = {0,0,0,0};
        const uint4* z4 = (const uint4*)g_z16;
        for (int j = tid; j < NE/2; j += ETHREADS) {
            uint4 u = __ldcg(&z4[j]);
            float z0[4], z1[4];
            unpack_half4(u.x, u.y, z0);
            unpack_half4(u.z, u.w, z1);
            #pragma unroll
            for (int e = 0; e < 2; e++) {
                const float* z = (e == 0) ? z0 : z1;
                float y[4];
                #pragma unroll
                for (int c = 0; c < 4; c++) y[c] = fmaxf(0.f, z[c] * a1[c] + b1[c]);
                #pragma unroll
                for (int c = 0; c < 4; c++) {
                    float z2 = bb2[c] + y[0]*W2[c] + y[1]*W2[4+c] + y[2]*W2[8+c] + y[3]*W2[12+c];
                    s[c] += z2; q[c] += z2*z2;
                }
            }
        }
        reduce_stats(s, q);
    }
    grid_barrier(&g_ebar_cnt, &g_ebar_rel, EGRID,
                 (double)NE, p.mg2, p.mbe2, g_ma2, g_mb2);

    // ---- phase 3: stream z + dst (.cg), message, scatter-add (2 edges/iter) --
    {
        float a1[4], b1[4], a2[4], b2a[4], W2[16], bb2[4];
        #pragma unroll
        for (int c = 0; c < 4; c++) {
            a1[c] = g_ma1[c]; b1[c] = g_mb1[c];
            a2[c] = g_ma2[c]; b2a[c] = g_mb2[c];
            bb2[c] = __ldg(&p.mb2[c]);
        }
        #pragma unroll
        for (int k = 0; k < 16; k++) W2[k] = __ldg(&p.mW2[k]);

        const int2* dst2 = (const int2*)p.dst;
        const uint4* z4 = (const uint4*)g_z16;
        for (int j = tid; j < NE/2; j += ETHREADS) {
            int2 di = __ldcg(&dst2[j]);
            uint4 u = __ldcg(&z4[j]);
            float z0[4], z1[4];
            unpack_half4(u.x, u.y, z0);
            unpack_half4(u.z, u.w, z1);
            float m0[4], m1[4];
            #pragma unroll
            for (int e = 0; e < 2; e++) {
                const float* z = (e == 0) ? z0 : z1;
                float* m = (e == 0) ? m0 : m1;
                float y[4];
                #pragma unroll
                for (int c = 0; c < 4; c++) y[c] = fmaxf(0.f, z[c] * a1[c] + b1[c]);
                #pragma unroll
                for (int c = 0; c < 4; c++) {
                    float z2 = bb2[c] + y[0]*W2[c] + y[1]*W2[4+c] + y[2]*W2[8+c] + y[3]*W2[12+c];
                    m[c] = fmaxf(0.f, z2 * a2[c] + b2a[c]);
                }
            }
            float4* a0 = &g_aggr[di.x];
            float4* a1p = &g_aggr[di.y];
            asm volatile("red.global.add.v4.f32 [%0], {%1, %2, %3, %4};"
                         :: "l"(a0), "f"(m0[0]), "f"(m0[1]), "f"(m0[2]), "f"(m0[3]) : "memory");
            asm volatile("red.global.add.v4.f32 [%0], {%1, %2, %3, %4};"
                         :: "l"(a1p), "f"(m1[0]), "f"(m1[1]), "f"(m1[2]), "f"(m1[3]) : "memory");
        }
    }
}

// ======================= node-update kernel =================================
__global__ void __launch_bounds__(UTB, 2) k_upd(P p) {
    const int tid = blockIdx.x * UTB + threadIdx.x;
    const int n0 = tid, n1 = tid + UTHREADS;
    const bool v0 = (n0 < NN), v1 = (n1 < NN);

    float x0[8], x1[8];
    if (v0) {
        float2 ps = __ldg((const float2*)&p.pos[2*n0]);
        float2 vl = __ldg((const float2*)&p.vel[2*n0]);
        float4 ag = g_aggr[n0];
        x0[0]=ps.x; x0[1]=ps.y; x0[2]=vl.x; x0[3]=vl.y;
        x0[4]=ag.x; x0[5]=ag.y; x0[6]=ag.z; x0[7]=ag.w;
    }
    if (v1) {
        float2 ps = __ldg((const float2*)&p.pos[2*n1]);
        float2 vl = __ldg((const float2*)&p.vel[2*n1]);
        float4 ag = g_aggr[n1];
        x1[0]=ps.x; x1[1]=ps.y; x1[2]=vl.x; x1[3]=vl.y;
        x1[4]=ag.x; x1[5]=ag.y; x1[6]=ag.z; x1[7]=ag.w;
    }

    // ---- phase A: layer-1 pre-BN (registers) + stats ----
    float zu0[4], zu1[4];
    {
        float W[32], bb[4];
        #pragma unroll
        for (int k = 0; k < 32; k++) W[k] = __ldg(&p.uW1[k]);
        #pragma unroll
        for (int c = 0; c < 4; c++) bb[c] = __ldg(&p.ub1[c]);

        float s[4] = {0,0,0,0}, q[4] = {0,0,0,0};
        if (v0) {
            #pragma unroll
            for (int c = 0; c < 4; c++) {
                float acc = bb[c];
                #pragma unroll
                for (int k = 0; k < 8; k++) acc += x0[k] * W[k*4 + c];
                zu0[c] = acc; s[c] += acc; q[c] += acc*acc;
            }
        }
        if (v1) {
            #pragma unroll
            for (int c = 0; c < 4; c++) {
                float acc = bb[c];
                #pragma unroll
                for (int k = 0; k < 8; k++) acc += x1[k] * W[k*4 + c];
                zu1[c] = acc; s[c] += acc; q[c] += acc*acc;
            }
        }
        reduce_stats(s, q);
    }
    grid_barrier(&g_ubar_cnt, &g_ubar_rel, UGRID,
                 (double)NN, p.ug1, p.ube1, g_ua1, g_ub1);

    // ---- phase B: layer-2 pre-BN (registers) + stats ----
    float z20[4], z21[4];
    {
        float a1[4], b1[4], W2[16], bb2[4];
        #pragma unroll
        for (int c = 0; c < 4; c++) { a1[c] = g_ua1[c]; b1[c] = g_ub1[c]; bb2[c] = __ldg(&p.ub2[c]); }
        #pragma unroll
        for (int k = 0; k < 16; k++) W2[k] = __ldg(&p.uW2[k]);

        float s[4] = {0,0,0,0}, q[4] = {0,0,0,0};
        if (v0) {
            float y[4];
            #pragma unroll
            for (int c = 0; c < 4; c++) y[c] = fmaxf(0.f, zu0[c] * a1[c] + b1[c]);
            #pragma unroll
            for (int c = 0; c < 4; c++) {
                z20[c] = bb2[c] + y[0]*W2[c] + y[1]*W2[4+c] + y[2]*W2[8+c] + y[3]*W2[12+c];
                s[c] += z20[c]; q[c] += z20[c]*z20[c];
            }
        }
        if (v1) {
            float y[4];
            #pragma unroll
            for (int c = 0; c < 4; c++) y[c] = fmaxf(0.f, zu1[c] * a1[c] + b1[c]);
            #pragma unroll
            for (int c = 0; c < 4; c++) {
                z21[c] = bb2[c] + y[0]*W2[c] + y[1]*W2[4+c] + y[2]*W2[8+c] + y[3]*W2[12+c];
                s[c] += z21[c]; q[c] += z21[c]*z21[c];
            }
        }
        reduce_stats(s, q);
    }
    grid_barrier(&g_ubar_cnt, &g_ubar_rel, UGRID,
                 (double)NN, p.ug2, p.ube2, g_ua2, g_ub2);

    // ---- phase C: final BN+ReLU + prediction head ----
    {
        float a2[4], b2[4], pW[8], pb0, pb1;
        #pragma unroll
        for (int c = 0; c < 4; c++) { a2[c] = g_ua2[c]; b2[c] = g_ub2[c]; }
        #pragma unroll
        for (int k = 0; k < 8; k++) pW[k] = __ldg(&p.pW[k]);
        pb0 = __ldg(&p.pb[0]); pb1 = __ldg(&p.pb[1]);

        if (v0) {
            float u[4];
            #pragma unroll
            for (int c = 0; c < 4; c++) u[c] = fmaxf(0.f, z20[c] * a2[c] + b2[c]);
            float o0 = pb0, o1 = pb1;
            #pragma unroll
            for (int k = 0; k < 4; k++) { o0 += u[k]*pW[k*2]; o1 += u[k]*pW[k*2+1]; }
            ((float2*)p.out)[n0] = make_float2(o0, o1);
        }
        if (v1) {
            float u[4];
            #pragma unroll
            for (int c = 0; c < 4; c++) u[c] = fmaxf(0.f, z21[c] * a2[c] + b2[c]);
            float o0 = pb0, o1 = pb1;
            #pragma unroll
            for (int k = 0; k < 4; k++) { o0 += u[k]*pW[k*2]; o1 += u[k]*pW[k*2+1]; }
            ((float2*)p.out)[n1] = make_float2(o0, o1);
        }
    }
}

// ---------------- launch -----------------------------------------------------
extern "C" void kernel_launch(void* const* d_in, const int* in_sizes, int n_in,
                              void* d_out, int out_size) {
    P p;
    p.pos = (const float*)d_in[0];
    p.vel = (const float*)d_in[1];
    const int* ei = (const int*)d_in[2];   // int32 (JAX canonicalizes int64 -> int32)
    p.src = ei;            // edge_index[0]
    p.dst = ei + NE;       // edge_index[1]
    p.mW1  = (const float*)d_in[3];  p.mb1  = (const float*)d_in[4];
    p.mg1  = (const float*)d_in[5];  p.mbe1 = (const float*)d_in[6];
    p.mW2  = (const float*)d_in[7];  p.mb2  = (const float*)d_in[8];
    p.mg2  = (const float*)d_in[9];  p.mbe2 = (const float*)d_in[10];
    p.uW1  = (const float*)d_in[11]; p.ub1  = (const float*)d_in[12];
    p.ug1  = (const float*)d_in[13]; p.ube1 = (const float*)d_in[14];
    p.uW2  = (const float*)d_in[15]; p.ub2  = (const float*)d_in[16];
    p.ug2  = (const float*)d_in[17]; p.ube2 = (const float*)d_in[18];
    p.pW   = (const float*)d_in[19]; p.pb   = (const float*)d_in[20];
    p.out  = (float*)d_out;

    k_edge<<<EGRID, ETB>>>(p);
    k_upd <<<UGRID, UTB>>>(p);
}

// round 11
// speedup vs baseline: 1.0437x; 1.0437x over previous
#include <cuda_runtime.h>
#include <cuda_bf16.h>
#include <cuda_fp16.h>

#define NN 100000
#define NE 6400000
#define EGRID 592
#define ETB 256
#define ETHREADS (EGRID * ETB)   // 151552, = 148 SMs x 4 blocks
#define UGRID 296
#define UTB 256
#define UTHREADS (UGRID * UTB)   // 75776,  = 148 SMs x 2 blocks
static constexpr float BN_EPS = 1e-5f;

// ---------------- scratch (static device arrays; no runtime alloc) ---------
__device__ float4 g_A[NN];            // h @ msg_W1[0:4]   (dst-side partial)
__device__ float4 g_B[NN];            // h @ msg_W1[4:8]+b (src-side partial)
__device__ uint2  g_z16[NE];          // per-edge layer-1 pre-BN, packed half4 (51.2 MB)
__device__ float4 g_aggr[NN];         // scatter-add target

__device__ double g_sum[4];
__device__ double g_sq[4];

// grid-barrier state (monotonic counters; each kernel resets the OTHER's)
__device__ unsigned          g_ebar_cnt;
__device__ volatile unsigned g_ebar_rel;
__device__ unsigned          g_ubar_cnt;
__device__ volatile unsigned g_ubar_rel;

__device__ float g_ma1[4], g_mb1[4];  // msg BN1 affine
__device__ float g_ma2[4], g_mb2[4];  // msg BN2 affine
__device__ float g_ua1[4], g_ub1[4];  // upd BN1 affine
__device__ float g_ua2[4], g_ub2[4];  // upd BN2 affine

struct P {
    const float* pos; const float* vel;
    const int* src; const int* dst;   // edge_index rows (int32)
    const float *mW1,*mb1,*mg1,*mbe1,*mW2,*mb2,*mg2,*mbe2;
    const float *uW1,*ub1,*ug1,*ube1,*uW2,*ub2,*ug2,*ube2;
    const float *pW,*pb;
    float* out;
};

// ---------------- half4 pack/unpack -----------------------------------------
__device__ __forceinline__ uint2 pack_half4(float x, float y, float z, float w) {
    __half2 a = __floats2half2_rn(x, y);
    __half2 b = __floats2half2_rn(z, w);
    uint2 u;
    u.x = *reinterpret_cast<unsigned*>(&a);
    u.y = *reinterpret_cast<unsigned*>(&b);
    return u;
}
__device__ __forceinline__ void unpack_half4(unsigned lo, unsigned hi, float z[4]) {
    __half2 a = *reinterpret_cast<__half2*>(&lo);
    __half2 b = *reinterpret_cast<__half2*>(&hi);
    float2 f0 = __half22float2(a), f1 = __half22float2(b);
    z[0] = f0.x; z[1] = f0.y; z[2] = f1.x; z[3] = f1.y;
}

// ---------------- block-level stats reduce -> global atomics ----------------
__device__ __forceinline__ void reduce_stats(float s[4], float q[4]) {
    #pragma unroll
    for (int o = 16; o > 0; o >>= 1) {
        #pragma unroll
        for (int c = 0; c < 4; c++) {
            s[c] += __shfl_down_sync(0xffffffffu, s[c], o);
            q[c] += __shfl_down_sync(0xffffffffu, q[c], o);
        }
    }
    __shared__ float shs[4][8], shq[4][8];
    int w = threadIdx.x >> 5;
    if ((threadIdx.x & 31) == 0) {
        #pragma unroll
        for (int c = 0; c < 4; c++) { shs[c][w] = s[c]; shq[c][w] = q[c]; }
    }
    __syncthreads();
    if (threadIdx.x == 0) {
        int nw = blockDim.x >> 5;
        #pragma unroll
        for (int c = 0; c < 4; c++) {
            double ts = 0.0, tq = 0.0;
            for (int i = 0; i < nw; i++) { ts += (double)shs[c][i]; tq += (double)shq[c][i]; }
            atomicAdd(&g_sum[c], ts);
            atomicAdd(&g_sq[c],  tq);
        }
    }
}

// finalize BN affine from global moments (VOLATILE reads: L1 may hold stale
// lines from a previous finalize within this same launch; atomics only hit L2)
__device__ __forceinline__ void bn_finalize(double count, const float* gamma, const float* beta,
                                            float* aout, float* bout) {
    #pragma unroll
    for (int c = 0; c < 4; c++) {
        double m = ((volatile double*)g_sum)[c] / count;
        double v = ((volatile double*)g_sq)[c] / count - m * m;
        float  al = __ldg(&gamma[c]) * rsqrtf((float)v + BN_EPS);
        aout[c] = al;
        bout[c] = __ldg(&beta[c]) - (float)m * al;
        g_sum[c] = 0.0; g_sq[c] = 0.0;
    }
}

// grid-wide barrier; last arriver optionally runs the BN finalize before release.
// Requires ALL blocks of the grid co-resident (grid == exact SM capacity).
__device__ __forceinline__ void grid_barrier(unsigned* cnt, volatile unsigned* rel,
                                             int phase, int grid,
                                             double count = 0.0,
                                             const float* gamma = nullptr,
                                             const float* beta  = nullptr,
                                             float* aout = nullptr, float* bout = nullptr) {
    __threadfence();
    __syncthreads();
    if (threadIdx.x == 0) {
        unsigned old = atomicAdd(cnt, 1u);
        if (old == (unsigned)(phase * grid + grid - 1)) {
            if (gamma) bn_finalize(count, gamma, beta, aout, bout);
            __threadfence();
            *rel = (unsigned)(phase + 1);
        } else {
            while (*rel <= (unsigned)phase) __nanosleep(64);
        }
        __threadfence();
    }
    __syncthreads();
}

// ======================= fused edge kernel ==================================
// phase0: node precompute   -> barrier
// phase1: gather+store z, BN1 stats -> barrier(+fin BN1)
// phase2: stream z, BN2 stats       -> barrier(+fin BN2)
// phase3: stream z+dst, message, scatter-add; kernel exit = sync
__global__ void __launch_bounds__(ETB, 4) k_edge(P p) {
    const int tid = blockIdx.x * ETB + threadIdx.x;

    // ---- phase 0: per-node precompute + state reset ----
    if (tid == 0) {
        g_ubar_cnt = 0; g_ubar_rel = 0;   // reset k_upd's barrier for this replay
        #pragma unroll
        for (int c = 0; c < 4; c++) { g_sum[c] = 0.0; g_sq[c] = 0.0; }
    }
    if (tid < NN) {
        float h0 = __ldg(&p.pos[2*tid]),  h1 = __ldg(&p.pos[2*tid+1]);
        float h2 = __ldg(&p.vel[2*tid]),  h3 = __ldg(&p.vel[2*tid+1]);
        float A[4], B[4];
        #pragma unroll
        for (int c = 0; c < 4; c++) {
            A[c] = h0*__ldg(&p.mW1[ 0+c]) + h1*__ldg(&p.mW1[ 4+c])
                 + h2*__ldg(&p.mW1[ 8+c]) + h3*__ldg(&p.mW1[12+c]);
            B[c] = __ldg(&p.mb1[c])
                 + h0*__ldg(&p.mW1[16+c]) + h1*__ldg(&p.mW1[20+c])
                 + h2*__ldg(&p.mW1[24+c]) + h3*__ldg(&p.mW1[28+c]);
        }
        g_A[tid]    = make_float4(A[0], A[1], A[2], A[3]);
        g_B[tid]    = make_float4(B[0], B[1], B[2], B[3]);
        g_aggr[tid] = make_float4(0.f, 0.f, 0.f, 0.f);
    }
    grid_barrier(&g_ebar_cnt, &g_ebar_rel, 0, EGRID);

    // ---- phase 1: gather once, pack-store z, layer-1 stats (2 edges/iter) ----
    {
        float s[4] = {0,0,0,0}, q[4] = {0,0,0,0};
        const int2* src2 = (const int2*)p.src;
        const int2* dst2 = (const int2*)p.dst;
        uint4* z4 = (uint4*)g_z16;
        for (int j = tid; j < NE/2; j += ETHREADS) {
            int2 si = __ldg(&src2[j]);
            int2 di = __ldg(&dst2[j]);
            float4 A0 = g_A[di.x], B0 = g_B[si.x];
            float4 A1 = g_A[di.y], B1 = g_B[si.y];
            float z0[4] = {A0.x+B0.x, A0.y+B0.y, A0.z+B0.z, A0.w+B0.w};
            float z1[4] = {A1.x+B1.x, A1.y+B1.y, A1.z+B1.z, A1.w+B1.w};
            uint2 u0 = pack_half4(z0[0], z0[1], z0[2], z0[3]);
            uint2 u1 = pack_half4(z1[0], z1[1], z1[2], z1[3]);
            z4[j] = make_uint4(u0.x, u0.y, u1.x, u1.y);
            #pragma unroll
            for (int c = 0; c < 4; c++) {
                s[c] += z0[c] + z1[c];
                q[c] += z0[c]*z0[c] + z1[c]*z1[c];
            }
        }
        reduce_stats(s, q);
    }
    grid_barrier(&g_ebar_cnt, &g_ebar_rel, 1, EGRID,
                 (double)NE, p.mg1, p.mbe1, g_ma1, g_mb1);

    // ---- phase 2: stream z, layer-2 stats (2 edges/iter) ----
    {
        float a1[4], b1[4], W2[16], bb2[4];
        #pragma unroll
        for (int c = 0; c < 4; c++) { a1[c] = g_ma1[c]; b1[c] = g_mb1[c]; bb2[c] = __ldg(&p.mb2[c]); }
        #pragma unroll
        for (int k = 0; k < 16; k++) W2[k] = __ldg(&p.mW2[k]);

        float s[4] = {0,0,0,0}, q[4] = {0,0,0,0};
        const uint4* z4 = (const uint4*)g_z16;
        for (int j = tid; j < NE/2; j += ETHREADS) {
            uint4 u = __ldg(&z4[j]);
            float z0[4], z1[4];
            unpack_half4(u.x, u.y, z0);
            unpack_half4(u.z, u.w, z1);
            #pragma unroll
            for (int e = 0; e < 2; e++) {
                const float* z = (e == 0) ? z0 : z1;
                float y[4];
                #pragma unroll
                for (int c = 0; c < 4; c++) y[c] = fmaxf(0.f, z[c] * a1[c] + b1[c]);
                #pragma unroll
                for (int c = 0; c < 4; c++) {
                    float z2 = bb2[c] + y[0]*W2[c] + y[1]*W2[4+c] + y[2]*W2[8+c] + y[3]*W2[12+c];
                    s[c] += z2; q[c] += z2*z2;
                }
            }
        }
        reduce_stats(s, q);
    }
    grid_barrier(&g_ebar_cnt, &g_ebar_rel, 2, EGRID,
                 (double)NE, p.mg2, p.mbe2, g_ma2, g_mb2);

    // ---- phase 3: stream z + dst, message, scatter-add (2 edges/iter) ----
    {
        float a1[4], b1[4], a2[4], b2a[4], W2[16], bb2[4];
        #pragma unroll
        for (int c = 0; c < 4; c++) {
            a1[c] = g_ma1[c]; b1[c] = g_mb1[c];
            a2[c] = g_ma2[c]; b2a[c] = g_mb2[c];
            bb2[c] = __ldg(&p.mb2[c]);
        }
        #pragma unroll
        for (int k = 0; k < 16; k++) W2[k] = __ldg(&p.mW2[k]);

        const int2* dst2 = (const int2*)p.dst;
        const uint4* z4 = (const uint4*)g_z16;
        for (int j = tid; j < NE/2; j += ETHREADS) {
            int2 di = __ldg(&dst2[j]);
            uint4 u = __ldg(&z4[j]);
            float z0[4], z1[4];
            unpack_half4(u.x, u.y, z0);
            unpack_half4(u.z, u.w, z1);
            float m0[4], m1[4];
            #pragma unroll
            for (int e = 0; e < 2; e++) {
                const float* z = (e == 0) ? z0 : z1;
                float* m = (e == 0) ? m0 : m1;
                float y[4];
                #pragma unroll
                for (int c = 0; c < 4; c++) y[c] = fmaxf(0.f, z[c] * a1[c] + b1[c]);
                #pragma unroll
                for (int c = 0; c < 4; c++) {
                    float z2 = bb2[c] + y[0]*W2[c] + y[1]*W2[4+c] + y[2]*W2[8+c] + y[3]*W2[12+c];
                    m[c] = fmaxf(0.f, z2 * a2[c] + b2a[c]);
                }
            }
            float4* a0 = &g_aggr[di.x];
            float4* a1p = &g_aggr[di.y];
            asm volatile("red.global.add.v4.f32 [%0], {%1, %2, %3, %4};"
                         :: "l"(a0), "f"(m0[0]), "f"(m0[1]), "f"(m0[2]), "f"(m0[3]) : "memory");
            asm volatile("red.global.add.v4.f32 [%0], {%1, %2, %3, %4};"
                         :: "l"(a1p), "f"(m1[0]), "f"(m1[1]), "f"(m1[2]), "f"(m1[3]) : "memory");
        }
    }
}

// ======================= fused node-update kernel ===========================
// Each thread owns up to 2 nodes; zu/z2 stay in registers across phases.
__global__ void __launch_bounds__(UTB, 2) k_upd(P p) {
    const int tid = blockIdx.x * UTB + threadIdx.x;
    if (tid == 0) { g_ebar_cnt = 0; g_ebar_rel = 0; }  // reset edge barrier for next replay

    const int n0 = tid, n1 = tid + UTHREADS;
    const bool v0 = (n0 < NN), v1 = (n1 < NN);

    float x0[8], x1[8];
    if (v0) {
        float2 ps = __ldg((const float2*)&p.pos[2*n0]);
        float2 vl = __ldg((const float2*)&p.vel[2*n0]);
        float4 ag = g_aggr[n0];
        x0[0]=ps.x; x0[1]=ps.y; x0[2]=vl.x; x0[3]=vl.y;
        x0[4]=ag.x; x0[5]=ag.y; x0[6]=ag.z; x0[7]=ag.w;
    }
    if (v1) {
        float2 ps = __ldg((const float2*)&p.pos[2*n1]);
        float2 vl = __ldg((const float2*)&p.vel[2*n1]);
        float4 ag = g_aggr[n1];
        x1[0]=ps.x; x1[1]=ps.y; x1[2]=vl.x; x1[3]=vl.y;
        x1[4]=ag.x; x1[5]=ag.y; x1[6]=ag.z; x1[7]=ag.w;
    }

    // ---- phase 0: layer-1 pre-BN (registers) + stats ----
    float zu0[4], zu1[4];
    {
        float W[32], bb[4];
        #pragma unroll
        for (int k = 0; k < 32; k++) W[k] = __ldg(&p.uW1[k]);
        #pragma unroll
        for (int c = 0; c < 4; c++) bb[c] = __ldg(&p.ub1[c]);

        float s[4] = {0,0,0,0}, q[4] = {0,0,0,0};
        if (v0) {
            #pragma unroll
            for (int c = 0; c < 4; c++) {
                float acc = bb[c];
                #pragma unroll
                for (int k = 0; k < 8; k++) acc += x0[k] * W[k*4 + c];
                zu0[c] = acc; s[c] += acc; q[c] += acc*acc;
            }
        }
        if (v1) {
            #pragma unroll
            for (int c = 0; c < 4; c++) {
                float acc = bb[c];
                #pragma unroll
                for (int k = 0; k < 8; k++) acc += x1[k] * W[k*4 + c];
                zu1[c] = acc; s[c] += acc; q[c] += acc*acc;
            }
        }
        reduce_stats(s, q);
    }
    grid_barrier(&g_ubar_cnt, &g_ubar_rel, 0, UGRID,
                 (double)NN, p.ug1, p.ube1, g_ua1, g_ub1);

    // ---- phase 1: layer-2 pre-BN (registers) + stats ----
    float z20[4], z21[4];
    {
        float a1[4], b1[4], W2[16], bb2[4];
        #pragma unroll
        for (int c = 0; c < 4; c++) { a1[c] = g_ua1[c]; b1[c] = g_ub1[c]; bb2[c] = __ldg(&p.ub2[c]); }
        #pragma unroll
        for (int k = 0; k < 16; k++) W2[k] = __ldg(&p.uW2[k]);

        float s[4] = {0,0,0,0}, q[4] = {0,0,0,0};
        if (v0) {
            float y[4];
            #pragma unroll
            for (int c = 0; c < 4; c++) y[c] = fmaxf(0.f, zu0[c] * a1[c] + b1[c]);
            #pragma unroll
            for (int c = 0; c < 4; c++) {
                z20[c] = bb2[c] + y[0]*W2[c] + y[1]*W2[4+c] + y[2]*W2[8+c] + y[3]*W2[12+c];
                s[c] += z20[c]; q[c] += z20[c]*z20[c];
            }
        }
        if (v1) {
            float y[4];
            #pragma unroll
            for (int c = 0; c < 4; c++) y[c] = fmaxf(0.f, zu1[c] * a1[c] + b1[c]);
            #pragma unroll
            for (int c = 0; c < 4; c++) {
                z21[c] = bb2[c] + y[0]*W2[c] + y[1]*W2[4+c] + y[2]*W2[8+c] + y[3]*W2[12+c];
                s[c] += z21[c]; q[c] += z21[c]*z21[c];
            }
        }
        reduce_stats(s, q);
    }
    grid_barrier(&g_ubar_cnt, &g_ubar_rel, 1, UGRID,
                 (double)NN, p.ug2, p.ube2, g_ua2, g_ub2);

    // ---- phase 2: final BN+ReLU + prediction head ----
    {
        float a2[4], b2[4], pW[8], pb0, pb1;
        #pragma unroll
        for (int c = 0; c < 4; c++) { a2[c] = g_ua2[c]; b2[c] = g_ub2[c]; }
        #pragma unroll
        for (int k = 0; k < 8; k++) pW[k] = __ldg(&p.pW[k]);
        pb0 = __ldg(&p.pb[0]); pb1 = __ldg(&p.pb[1]);

        if (v0) {
            float u[4];
            #pragma unroll
            for (int c = 0; c < 4; c++) u[c] = fmaxf(0.f, z20[c] * a2[c] + b2[c]);
            float o0 = pb0, o1 = pb1;
            #pragma unroll
            for (int k = 0; k < 4; k++) { o0 += u[k]*pW[k*2]; o1 += u[k]*pW[k*2+1]; }
            ((float2*)p.out)[n0] = make_float2(o0, o1);
        }
        if (v1) {
            float u[4];
            #pragma unroll
            for (int c = 0; c < 4; c++) u[c] = fmaxf(0.f, z21[c] * a2[c] + b2[c]);
            float o0 = pb0, o1 = pb1;
            #pragma unroll
            for (int k = 0; k < 4; k++) { o0 += u[k]*pW[k*2]; o1 += u[k]*pW[k*2+1]; }
            ((float2*)p.out)[n1] = make_float2(o0, o1);
        }
    }
}

// ---------------- launch -----------------------------------------------------
extern "C" void kernel_launch(void* const* d_in, const int* in_sizes, int n_in,
                              void* d_out, int out_size) {
    P p;
    p.pos = (const float*)d_in[0];
    p.vel = (const float*)d_in[1];
    const int* ei = (const int*)d_in[2];   // int32 (JAX canonicalizes int64 -> int32)
    p.src = ei;            // edge_index[0]
    p.dst = ei + NE;       // edge_index[1]
    p.mW1  = (const float*)d_in[3];  p.mb1  = (const float*)d_in[4];
    p.mg1  = (const float*)d_in[5];  p.mbe1 = (const float*)d_in[6];
    p.mW2  = (const float*)d_in[7];  p.mb2  = (const float*)d_in[8];
    p.mg2  = (const float*)d_in[9];  p.mbe2 = (const float*)d_in[10];
    p.uW1  = (const float*)d_in[11]; p.ub1  = (const float*)d_in[12];
    p.ug1  = (const float*)d_in[13]; p.ube1 = (const float*)d_in[14];
    p.uW2  = (const float*)d_in[15]; p.ub2  = (const float*)d_in[16];
    p.ug2  = (const float*)d_in[17]; p.ube2 = (const float*)d_in[18];
    p.pW   = (const float*)d_in[19]; p.pb   = (const float*)d_in[20];
    p.out  = (float*)d_out;

    k_edge<<<EGRID, ETB>>>(p);
    k_upd <<<UGRID, UTB>>>(p);
}

// round 12
// speedup vs baseline: 1.0439x; 1.0002x over previous
#include <cuda_runtime.h>
#include <cuda_bf16.h>
#include <cuda_fp16.h>

#define NN 100000
#define NE 6400000
#define EGRID 592
#define ETB 256
#define ETHREADS (EGRID * ETB)   // 151552, = 148 SMs x 4 blocks
#define UGRID 296
#define UTB 256
#define UTHREADS (UGRID * UTB)   // 75776,  = 148 SMs x 2 blocks
static constexpr float BN_EPS = 1e-5f;

// ---------------- scratch (static device arrays; no runtime alloc) ---------
__device__ float4 g_A[NN];            // h @ msg_W1[0:4]   (dst-side partial)
__device__ float4 g_B[NN];            // h @ msg_W1[4:8]+b (src-side partial)
__device__ uint2  g_z16[NE];          // per-edge layer-1 pre-BN, packed half4 (51.2 MB)
__device__ float4 g_aggr[NN];         // scatter-add target

__device__ double g_sum[4];
__device__ double g_sq[4];

// grid-barrier state (each kernel resets the OTHER's; k_upd resets after PDL sync)
__device__ unsigned          g_ebar_cnt;
__device__ volatile unsigned g_ebar_rel;
__device__ unsigned          g_ubar_cnt;
__device__ volatile unsigned g_ubar_rel;

__device__ float g_ma1[4], g_mb1[4];  // msg BN1 affine
__device__ float g_ma2[4], g_mb2[4];  // msg BN2 affine
__device__ float g_ua1[4], g_ub1[4];  // upd BN1 affine
__device__ float g_ua2[4], g_ub2[4];  // upd BN2 affine

struct P {
    const float* pos; const float* vel;
    const int* src; const int* dst;   // edge_index rows (int32)
    const float *mW1,*mb1,*mg1,*mbe1,*mW2,*mb2,*mg2,*mbe2;
    const float *uW1,*ub1,*ug1,*ube1,*uW2,*ub2,*ug2,*ube2;
    const float *pW,*pb;
    float* out;
};

// ---------------- half4 pack/unpack -----------------------------------------
__device__ __forceinline__ uint2 pack_half4(float x, float y, float z, float w) {
    __half2 a = __floats2half2_rn(x, y);
    __half2 b = __floats2half2_rn(z, w);
    uint2 u;
    u.x = *reinterpret_cast<unsigned*>(&a);
    u.y = *reinterpret_cast<unsigned*>(&b);
    return u;
}
__device__ __forceinline__ void unpack_half4(unsigned lo, unsigned hi, float z[4]) {
    __half2 a = *reinterpret_cast<__half2*>(&lo);
    __half2 b = *reinterpret_cast<__half2*>(&hi);
    float2 f0 = __half22float2(a), f1 = __half22float2(b);
    z[0] = f0.x; z[1] = f0.y; z[2] = f1.x; z[3] = f1.y;
}

// ---------------- block-level stats reduce -> global atomics ----------------
__device__ __forceinline__ void reduce_stats(float s[4], float q[4]) {
    #pragma unroll
    for (int o = 16; o > 0; o >>= 1) {
        #pragma unroll
        for (int c = 0; c < 4; c++) {
            s[c] += __shfl_down_sync(0xffffffffu, s[c], o);
            q[c] += __shfl_down_sync(0xffffffffu, q[c], o);
        }
    }
    __shared__ float shs[4][8], shq[4][8];
    int w = threadIdx.x >> 5;
    if ((threadIdx.x & 31) == 0) {
        #pragma unroll
        for (int c = 0; c < 4; c++) { shs[c][w] = s[c]; shq[c][w] = q[c]; }
    }
    __syncthreads();
    if (threadIdx.x == 0) {
        int nw = blockDim.x >> 5;
        #pragma unroll
        for (int c = 0; c < 4; c++) {
            double ts = 0.0, tq = 0.0;
            for (int i = 0; i < nw; i++) { ts += (double)shs[c][i]; tq += (double)shq[c][i]; }
            atomicAdd(&g_sum[c], ts);
            atomicAdd(&g_sq[c],  tq);
        }
    }
}

// finalize BN affine from global moments (VOLATILE reads: L1 may hold stale
// lines from a previous finalize within this same launch; atomics only hit L2)
__device__ __forceinline__ void bn_finalize(double count, const float* gamma, const float* beta,
                                            float* aout, float* bout) {
    #pragma unroll
    for (int c = 0; c < 4; c++) {
        double m = ((volatile double*)g_sum)[c] / count;
        double v = ((volatile double*)g_sq)[c] / count - m * m;
        float  al = __ldg(&gamma[c]) * rsqrtf((float)v + BN_EPS);
        aout[c] = al;
        bout[c] = __ldg(&beta[c]) - (float)m * al;
        g_sum[c] = 0.0; g_sq[c] = 0.0;
    }
}

// grid-wide barrier; last arriver optionally runs the BN finalize before release.
// Requires ALL blocks of the grid co-resident (grid == exact SM capacity).
__device__ __forceinline__ void grid_barrier(unsigned* cnt, volatile unsigned* rel,
                                             int phase, int grid,
                                             double count = 0.0,
                                             const float* gamma = nullptr,
                                             const float* beta  = nullptr,
                                             float* aout = nullptr, float* bout = nullptr) {
    __threadfence();
    __syncthreads();
    if (threadIdx.x == 0) {
        unsigned old = atomicAdd(cnt, 1u);
        if (old == (unsigned)(phase * grid + grid - 1)) {
            if (gamma) bn_finalize(count, gamma, beta, aout, bout);
            __threadfence();
            *rel = (unsigned)(phase + 1);
        } else {
            while (*rel <= (unsigned)phase) __nanosleep(64);
        }
        __threadfence();
    }
    __syncthreads();
}

// ======================= fused edge kernel ==================================
// phase0: node precompute   -> barrier
// phase1: gather+store z, BN1 stats -> barrier(+fin BN1)
// phase2: stream z, BN2 stats       -> barrier(+fin BN2)
// phase3: [PDL trigger] stream z+dst, message, scatter-add; kernel exit = sync
__global__ void __launch_bounds__(ETB, 4) k_edge(P p) {
    const int tid = blockIdx.x * ETB + threadIdx.x;

    // ---- phase 0: per-node precompute + state reset ----
    if (tid == 0) {
        g_ubar_cnt = 0; g_ubar_rel = 0;   // reset k_upd's barrier for this replay
        #pragma unroll
        for (int c = 0; c < 4; c++) { g_sum[c] = 0.0; g_sq[c] = 0.0; }
    }
    if (tid < NN) {
        float h0 = __ldg(&p.pos[2*tid]),  h1 = __ldg(&p.pos[2*tid+1]);
        float h2 = __ldg(&p.vel[2*tid]),  h3 = __ldg(&p.vel[2*tid+1]);
        float A[4], B[4];
        #pragma unroll
        for (int c = 0; c < 4; c++) {
            A[c] = h0*__ldg(&p.mW1[ 0+c]) + h1*__ldg(&p.mW1[ 4+c])
                 + h2*__ldg(&p.mW1[ 8+c]) + h3*__ldg(&p.mW1[12+c]);
            B[c] = __ldg(&p.mb1[c])
                 + h0*__ldg(&p.mW1[16+c]) + h1*__ldg(&p.mW1[20+c])
                 + h2*__ldg(&p.mW1[24+c]) + h3*__ldg(&p.mW1[28+c]);
        }
        g_A[tid]    = make_float4(A[0], A[1], A[2], A[3]);
        g_B[tid]    = make_float4(B[0], B[1], B[2], B[3]);
        g_aggr[tid] = make_float4(0.f, 0.f, 0.f, 0.f);
    }
    grid_barrier(&g_ebar_cnt, &g_ebar_rel, 0, EGRID);

    // ---- phase 1: gather once, pack-store z, layer-1 stats (2 edges/iter) ----
    {
        float s[4] = {0,0,0,0}, q[4] = {0,0,0,0};
        const int2* src2 = (const int2*)p.src;
        const int2* dst2 = (const int2*)p.dst;
        uint4* z4 = (uint4*)g_z16;
        for (int j = tid; j < NE/2; j += ETHREADS) {
            int2 si = __ldg(&src2[j]);
            int2 di = __ldg(&dst2[j]);
            float4 A0 = g_A[di.x], B0 = g_B[si.x];
            float4 A1 = g_A[di.y], B1 = g_B[si.y];
            float z0[4] = {A0.x+B0.x, A0.y+B0.y, A0.z+B0.z, A0.w+B0.w};
            float z1[4] = {A1.x+B1.x, A1.y+B1.y, A1.z+B1.z, A1.w+B1.w};
            uint2 u0 = pack_half4(z0[0], z0[1], z0[2], z0[3]);
            uint2 u1 = pack_half4(z1[0], z1[1], z1[2], z1[3]);
            z4[j] = make_uint4(u0.x, u0.y, u1.x, u1.y);
            #pragma unroll
            for (int c = 0; c < 4; c++) {
                s[c] += z0[c] + z1[c];
                q[c] += z0[c]*z0[c] + z1[c]*z1[c];
            }
        }
        reduce_stats(s, q);
    }
    grid_barrier(&g_ebar_cnt, &g_ebar_rel, 1, EGRID,
                 (double)NE, p.mg1, p.mbe1, g_ma1, g_mb1);

    // ---- phase 2: stream z, layer-2 stats (2 edges/iter) ----
    {
        float a1[4], b1[4], W2[16], bb2[4];
        #pragma unroll
        for (int c = 0; c < 4; c++) { a1[c] = g_ma1[c]; b1[c] = g_mb1[c]; bb2[c] = __ldg(&p.mb2[c]); }
        #pragma unroll
        for (int k = 0; k < 16; k++) W2[k] = __ldg(&p.mW2[k]);

        float s[4] = {0,0,0,0}, q[4] = {0,0,0,0};
        const uint4* z4 = (const uint4*)g_z16;
        for (int j = tid; j < NE/2; j += ETHREADS) {
            uint4 u = __ldg(&z4[j]);
            float z0[4], z1[4];
            unpack_half4(u.x, u.y, z0);
            unpack_half4(u.z, u.w, z1);
            #pragma unroll
            for (int e = 0; e < 2; e++) {
                const float* z = (e == 0) ? z0 : z1;
                float y[4];
                #pragma unroll
                for (int c = 0; c < 4; c++) y[c] = fmaxf(0.f, z[c] * a1[c] + b1[c]);
                #pragma unroll
                for (int c = 0; c < 4; c++) {
                    float z2 = bb2[c] + y[0]*W2[c] + y[1]*W2[4+c] + y[2]*W2[8+c] + y[3]*W2[12+c];
                    s[c] += z2; q[c] += z2*z2;
                }
            }
        }
        reduce_stats(s, q);
    }
    grid_barrier(&g_ebar_cnt, &g_ebar_rel, 2, EGRID,
                 (double)NE, p.mg2, p.mbe2, g_ma2, g_mb2);

    // PDL: all cross-block state (g_ebar, g_sum/g_sq, BN affines) is final for
    // this kernel; allow the dependent k_upd grid to begin launching now so it
    // overlaps with phase 3's scatter tail.
    cudaTriggerProgrammaticLaunchCompletion();

    // ---- phase 3: stream z + dst, message, scatter-add (2 edges/iter) ----
    {
        float a1[4], b1[4], a2[4], b2a[4], W2[16], bb2[4];
        #pragma unroll
        for (int c = 0; c < 4; c++) {
            a1[c] = g_ma1[c]; b1[c] = g_mb1[c];
            a2[c] = g_ma2[c]; b2a[c] = g_mb2[c];
            bb2[c] = __ldg(&p.mb2[c]);
        }
        #pragma unroll
        for (int k = 0; k < 16; k++) W2[k] = __ldg(&p.mW2[k]);

        const int2* dst2 = (const int2*)p.dst;
        const uint4* z4 = (const uint4*)g_z16;
        for (int j = tid; j < NE/2; j += ETHREADS) {
            int2 di = __ldg(&dst2[j]);
            uint4 u = __ldg(&z4[j]);
            float z0[4], z1[4];
            unpack_half4(u.x, u.y, z0);
            unpack_half4(u.z, u.w, z1);
            float m0[4], m1[4];
            #pragma unroll
            for (int e = 0; e < 2; e++) {
                const float* z = (e == 0) ? z0 : z1;
                float* m = (e == 0) ? m0 : m1;
                float y[4];
                #pragma unroll
                for (int c = 0; c < 4; c++) y[c] = fmaxf(0.f, z[c] * a1[c] + b1[c]);
                #pragma unroll
                for (int c = 0; c < 4; c++) {
                    float z2 = bb2[c] + y[0]*W2[c] + y[1]*W2[4+c] + y[2]*W2[8+c] + y[3]*W2[12+c];
                    m[c] = fmaxf(0.f, z2 * a2[c] + b2a[c]);
                }
            }
            float4* a0 = &g_aggr[di.x];
            float4* a1p = &g_aggr[di.y];
            asm volatile("red.global.add.v4.f32 [%0], {%1, %2, %3, %4};"
                         :: "l"(a0), "f"(m0[0]), "f"(m0[1]), "f"(m0[2]), "f"(m0[3]) : "memory");
            asm volatile("red.global.add.v4.f32 [%0], {%1, %2, %3, %4};"
                         :: "l"(a1p), "f"(m1[0]), "f"(m1[1]), "f"(m1[2]), "f"(m1[3]) : "memory");
        }
    }
}

// ======================= fused node-update kernel ===========================
// PDL secondary: prologue loads only read-only inputs, then waits for k_edge's
// writes (g_aggr, BN affines untouched by us) via cudaGridDependencySynchronize.
__global__ void __launch_bounds__(UTB, 2) k_upd(P p) {
    const int tid = blockIdx.x * UTB + threadIdx.x;
    const int n0 = tid, n1 = tid + UTHREADS;
    const bool v0 = (n0 < NN), v1 = (n1 < NN);

    // ---- prologue (overlaps with k_edge phase 3): read-only input loads ----
    float W[32], bb[4];
    #pragma unroll
    for (int k = 0; k < 32; k++) W[k] = __ldg(&p.uW1[k]);
    #pragma unroll
    for (int c = 0; c < 4; c++) bb[c] = __ldg(&p.ub1[c]);

    float x0[8], x1[8];
    if (v0) {
        float2 ps = __ldg((const float2*)&p.pos[2*n0]);
        float2 vl = __ldg((const float2*)&p.vel[2*n0]);
        x0[0]=ps.x; x0[1]=ps.y; x0[2]=vl.x; x0[3]=vl.y;
    }
    if (v1) {
        float2 ps = __ldg((const float2*)&p.pos[2*n1]);
        float2 vl = __ldg((const float2*)&p.vel[2*n1]);
        x1[0]=ps.x; x1[1]=ps.y; x1[2]=vl.x; x1[3]=vl.y;
    }

    // ---- wait for k_edge completion (scatter-adds + barrier state final) ----
    cudaGridDependencySynchronize();

    if (tid == 0) { g_ebar_cnt = 0; g_ebar_rel = 0; }  // reset edge barrier for next replay

    if (v0) {
        float4 ag = g_aggr[n0];
        x0[4]=ag.x; x0[5]=ag.y; x0[6]=ag.z; x0[7]=ag.w;
    }
    if (v1) {
        float4 ag = g_aggr[n1];
        x1[4]=ag.x; x1[5]=ag.y; x1[6]=ag.z; x1[7]=ag.w;
    }

    // ---- phase 0: layer-1 pre-BN (registers) + stats ----
    float zu0[4], zu1[4];
    {
        float s[4] = {0,0,0,0}, q[4] = {0,0,0,0};
        if (v0) {
            #pragma unroll
            for (int c = 0; c < 4; c++) {
                float acc = bb[c];
                #pragma unroll
                for (int k = 0; k < 8; k++) acc += x0[k] * W[k*4 + c];
                zu0[c] = acc; s[c] += acc; q[c] += acc*acc;
            }
        }
        if (v1) {
            #pragma unroll
            for (int c = 0; c < 4; c++) {
                float acc = bb[c];
                #pragma unroll
                for (int k = 0; k < 8; k++) acc += x1[k] * W[k*4 + c];
                zu1[c] = acc; s[c] += acc; q[c] += acc*acc;
            }
        }
        reduce_stats(s, q);
    }
    grid_barrier(&g_ubar_cnt, &g_ubar_rel, 0, UGRID,
                 (double)NN, p.ug1, p.ube1, g_ua1, g_ub1);

    // ---- phase 1: layer-2 pre-BN (registers) + stats ----
    float z20[4], z21[4];
    {
        float a1[4], b1[4], W2[16], bb2[4];
        #pragma unroll
        for (int c = 0; c < 4; c++) { a1[c] = g_ua1[c]; b1[c] = g_ub1[c]; bb2[c] = __ldg(&p.ub2[c]); }
        #pragma unroll
        for (int k = 0; k < 16; k++) W2[k] = __ldg(&p.uW2[k]);

        float s[4] = {0,0,0,0}, q[4] = {0,0,0,0};
        if (v0) {
            float y[4];
            #pragma unroll
            for (int c = 0; c < 4; c++) y[c] = fmaxf(0.f, zu0[c] * a1[c] + b1[c]);
            #pragma unroll
            for (int c = 0; c < 4; c++) {
                z20[c] = bb2[c] + y[0]*W2[c] + y[1]*W2[4+c] + y[2]*W2[8+c] + y[3]*W2[12+c];
                s[c] += z20[c]; q[c] += z20[c]*z20[c];
            }
        }
        if (v1) {
            float y[4];
            #pragma unroll
            for (int c = 0; c < 4; c++) y[c] = fmaxf(0.f, zu1[c] * a1[c] + b1[c]);
            #pragma unroll
            for (int c = 0; c < 4; c++) {
                z21[c] = bb2[c] + y[0]*W2[c] + y[1]*W2[4+c] + y[2]*W2[8+c] + y[3]*W2[12+c];
                s[c] += z21[c]; q[c] += z21[c]*z21[c];
            }
        }
        reduce_stats(s, q);
    }
    grid_barrier(&g_ubar_cnt, &g_ubar_rel, 1, UGRID,
                 (double)NN, p.ug2, p.ube2, g_ua2, g_ub2);

    // ---- phase 2: final BN+ReLU + prediction head ----
    {
        float a2[4], b2[4], pW[8], pb0, pb1;
        #pragma unroll
        for (int c = 0; c < 4; c++) { a2[c] = g_ua2[c]; b2[c] = g_ub2[c]; }
        #pragma unroll
        for (int k = 0; k < 8; k++) pW[k] = __ldg(&p.pW[k]);
        pb0 = __ldg(&p.pb[0]); pb1 = __ldg(&p.pb[1]);

        if (v0) {
            float u[4];
            #pragma unroll
            for (int c = 0; c < 4; c++) u[c] = fmaxf(0.f, z20[c] * a2[c] + b2[c]);
            float o0 = pb0, o1 = pb1;
            #pragma unroll
            for (int k = 0; k < 4; k++) { o0 += u[k]*pW[k*2]; o1 += u[k]*pW[k*2+1]; }
            ((float2*)p.out)[n0] = make_float2(o0, o1);
        }
        if (v1) {
            float u[4];
            #pragma unroll
            for (int c = 0; c < 4; c++) u[c] = fmaxf(0.f, z21[c] * a2[c] + b2[c]);
            float o0 = pb0, o1 = pb1;
            #pragma unroll
            for (int k = 0; k < 4; k++) { o0 += u[k]*pW[k*2]; o1 += u[k]*pW[k*2+1]; }
            ((float2*)p.out)[n1] = make_float2(o0, o1);
        }
    }
}

// ---------------- launch -----------------------------------------------------
extern "C" void kernel_launch(void* const* d_in, const int* in_sizes, int n_in,
                              void* d_out, int out_size) {
    P p;
    p.pos = (const float*)d_in[0];
    p.vel = (const float*)d_in[1];
    const int* ei = (const int*)d_in[2];   // int32 (JAX canonicalizes int64 -> int32)
    p.src = ei;            // edge_index[0]
    p.dst = ei + NE;       // edge_index[1]
    p.mW1  = (const float*)d_in[3];  p.mb1  = (const float*)d_in[4];
    p.mg1  = (const float*)d_in[5];  p.mbe1 = (const float*)d_in[6];
    p.mW2  = (const float*)d_in[7];  p.mb2  = (const float*)d_in[8];
    p.mg2  = (const float*)d_in[9];  p.mbe2 = (const float*)d_in[10];
    p.uW1  = (const float*)d_in[11]; p.ub1  = (const float*)d_in[12];
    p.ug1  = (const float*)d_in[13]; p.ube1 = (const float*)d_in[14];
    p.uW2  = (const float*)d_in[15]; p.ub2  = (const float*)d_in[16];
    p.ug2  = (const float*)d_in[17]; p.ube2 = (const float*)d_in[18];
    p.pW   = (const float*)d_in[19]; p.pb   = (const float*)d_in[20];
    p.out  = (float*)d_out;

    k_edge<<<EGRID, ETB>>>(p);

    // k_upd as PDL secondary: may begin launching once k_edge triggers
    // programmatic completion (start of its phase 3).
    cudaLaunchConfig_t cfg = {};
    cfg.gridDim  = dim3(UGRID, 1, 1);
    cfg.blockDim = dim3(UTB, 1, 1);
    cfg.dynamicSmemBytes = 0;
    cfg.stream = 0;
    cudaLaunchAttribute attrs[1];
    attrs[0].id = cudaLaunchAttributeProgrammaticStreamSerialization;
    attrs[0].val.programmaticStreamSerializationAllowed = 1;
    cfg.attrs = attrs;
    cfg.numAttrs = 1;
    cudaLaunchKernelEx(&cfg, k_upd, p);
}

// round 13
// speedup vs baseline: 1.0537x; 1.0094x over previous
#include <cuda_runtime.h>
#include <cuda_bf16.h>
#include <cuda_fp16.h>

#define NN 100000
#define NE 6400000
#define EGRID 592
#define ETB 256
#define ETHREADS (EGRID * ETB)   // 151552, = 148 SMs x 4 blocks
#define UGRID 296
#define UTB 256
#define UTHREADS (UGRID * UTB)   // 75776,  = 148 SMs x 2 blocks
static constexpr float BN_EPS = 1e-5f;

// ---------------- scratch (static device arrays; no runtime alloc) ---------
__device__ float4 g_A[NN];            // h @ msg_W1[0:4]   (dst-side partial)
__device__ float4 g_B[NN];            // h @ msg_W1[4:8]+b (src-side partial)
__device__ uint2  g_z16[NE];          // per-edge layer-1 pre-BN, packed half4 (51.2 MB)
__device__ float4 g_aggr[NN];         // scatter-add target

__device__ double g_sum[4];
__device__ double g_sq[4];

// grid-barrier state (monotonic counters; each kernel resets the OTHER's)
__device__ unsigned          g_ebar_cnt;
__device__ volatile unsigned g_ebar_rel;
__device__ unsigned          g_ubar_cnt;
__device__ volatile unsigned g_ubar_rel;

__device__ float g_ma1[4], g_mb1[4];  // msg BN1 affine
__device__ float g_ma2[4], g_mb2[4];  // msg BN2 affine
__device__ float g_ua1[4], g_ub1[4];  // upd BN1 affine
__device__ float g_ua2[4], g_ub2[4];  // upd BN2 affine

struct P {
    const float* pos; const float* vel;
    const int* src; const int* dst;   // edge_index rows (int32)
    const float *mW1,*mb1,*mg1,*mbe1,*mW2,*mb2,*mg2,*mbe2;
    const float *uW1,*ub1,*ug1,*ube1,*uW2,*ub2,*ug2,*ube2;
    const float *pW,*pb;
    float* out;
};

// ---------------- half4 pack/unpack -----------------------------------------
__device__ __forceinline__ uint2 pack_half4(float x, float y, float z, float w) {
    __half2 a = __floats2half2_rn(x, y);
    __half2 b = __floats2half2_rn(z, w);
    uint2 u;
    u.x = *reinterpret_cast<unsigned*>(&a);
    u.y = *reinterpret_cast<unsigned*>(&b);
    return u;
}
__device__ __forceinline__ void unpack_half4(unsigned lo, unsigned hi, float z[4]) {
    __half2 a = *reinterpret_cast<__half2*>(&lo);
    __half2 b = *reinterpret_cast<__half2*>(&hi);
    float2 f0 = __half22float2(a), f1 = __half22float2(b);
    z[0] = f0.x; z[1] = f0.y; z[2] = f1.x; z[3] = f1.y;
}

// ---------------- block-level stats reduce -> global atomics ----------------
__device__ __forceinline__ void reduce_stats(float s[4], float q[4]) {
    #pragma unroll
    for (int o = 16; o > 0; o >>= 1) {
        #pragma unroll
        for (int c = 0; c < 4; c++) {
            s[c] += __shfl_down_sync(0xffffffffu, s[c], o);
            q[c] += __shfl_down_sync(0xffffffffu, q[c], o);
        }
    }
    __shared__ float shs[4][8], shq[4][8];
    int w = threadIdx.x >> 5;
    if ((threadIdx.x & 31) == 0) {
        #pragma unroll
        for (int c = 0; c < 4; c++) { shs[c][w] = s[c]; shq[c][w] = q[c]; }
    }
    __syncthreads();
    if (threadIdx.x == 0) {
        int nw = blockDim.x >> 5;
        #pragma unroll
        for (int c = 0; c < 4; c++) {
            double ts = 0.0, tq = 0.0;
            for (int i = 0; i < nw; i++) { ts += (double)shs[c][i]; tq += (double)shq[c][i]; }
            atomicAdd(&g_sum[c], ts);
            atomicAdd(&g_sq[c],  tq);
        }
    }
}

// finalize BN affine from global moments (VOLATILE reads: L1 may hold stale
// lines from a previous finalize within this same launch; atomics only hit L2)
__device__ __forceinline__ void bn_finalize(double count, const float* gamma, const float* beta,
                                            float* aout, float* bout) {
    #pragma unroll
    for (int c = 0; c < 4; c++) {
        double m = ((volatile double*)g_sum)[c] / count;
        double v = ((volatile double*)g_sq)[c] / count - m * m;
        float  al = __ldg(&gamma[c]) * rsqrtf((float)v + BN_EPS);
        aout[c] = al;
        bout[c] = __ldg(&beta[c]) - (float)m * al;
        g_sum[c] = 0.0; g_sq[c] = 0.0;
    }
}

// grid-wide barrier; last arriver optionally runs the BN finalize before release.
// Requires ALL blocks of the grid co-resident (grid == exact SM capacity).
__device__ __forceinline__ void grid_barrier(unsigned* cnt, volatile unsigned* rel,
                                             int phase, int grid,
                                             double count = 0.0,
                                             const float* gamma = nullptr,
                                             const float* beta  = nullptr,
                                             float* aout = nullptr, float* bout = nullptr) {
    __threadfence();
    __syncthreads();
    if (threadIdx.x == 0) {
        unsigned old = atomicAdd(cnt, 1u);
        if (old == (unsigned)(phase * grid + grid - 1)) {
            if (gamma) bn_finalize(count, gamma, beta, aout, bout);
            __threadfence();
            *rel = (unsigned)(phase + 1);
        } else {
            while (*rel <= (unsigned)phase) __nanosleep(64);
        }
        __threadfence();
    }
    __syncthreads();
}

// ======================= fused edge kernel ==================================
// phase0: node precompute   -> barrier
// phase1: gather+store z, BN1 stats -> barrier(+fin BN1)
// phase2: stream z, BN2 stats       -> barrier(+fin BN2)
// phase3: stream z+dst, message, scatter-add; kernel exit = sync
__global__ void __launch_bounds__(ETB, 4) k_edge(P p) {
    const int tid = blockIdx.x * ETB + threadIdx.x;

    // ---- phase 0: per-node precompute + state reset ----
    if (tid == 0) {
        g_ubar_cnt = 0; g_ubar_rel = 0;   // reset k_upd's barrier for this replay
        #pragma unroll
        for (int c = 0; c < 4; c++) { g_sum[c] = 0.0; g_sq[c] = 0.0; }
    }
    if (tid < NN) {
        float h0 = __ldg(&p.pos[2*tid]),  h1 = __ldg(&p.pos[2*tid+1]);
        float h2 = __ldg(&p.vel[2*tid]),  h3 = __ldg(&p.vel[2*tid+1]);
        float A[4], B[4];
        #pragma unroll
        for (int c = 0; c < 4; c++) {
            A[c] = h0*__ldg(&p.mW1[ 0+c]) + h1*__ldg(&p.mW1[ 4+c])
                 + h2*__ldg(&p.mW1[ 8+c]) + h3*__ldg(&p.mW1[12+c]);
            B[c] = __ldg(&p.mb1[c])
                 + h0*__ldg(&p.mW1[16+c]) + h1*__ldg(&p.mW1[20+c])
                 + h2*__ldg(&p.mW1[24+c]) + h3*__ldg(&p.mW1[28+c]);
        }
        g_A[tid]    = make_float4(A[0], A[1], A[2], A[3]);
        g_B[tid]    = make_float4(B[0], B[1], B[2], B[3]);
        g_aggr[tid] = make_float4(0.f, 0.f, 0.f, 0.f);
    }
    grid_barrier(&g_ebar_cnt, &g_ebar_rel, 0, EGRID);

    // ---- phase 1: gather once, pack-store z, layer-1 stats (2 edges/iter) ----
    {
        float s[4] = {0,0,0,0}, q[4] = {0,0,0,0};
        const int2* src2 = (const int2*)p.src;
        const int2* dst2 = (const int2*)p.dst;
        uint4* z4 = (uint4*)g_z16;
        for (int j = tid; j < NE/2; j += ETHREADS) {
            int2 si = __ldg(&src2[j]);
            int2 di = __ldg(&dst2[j]);
            float4 A0 = g_A[di.x], B0 = g_B[si.x];
            float4 A1 = g_A[di.y], B1 = g_B[si.y];
            float z0[4] = {A0.x+B0.x, A0.y+B0.y, A0.z+B0.z, A0.w+B0.w};
            float z1[4] = {A1.x+B1.x, A1.y+B1.y, A1.z+B1.z, A1.w+B1.w};
            uint2 u0 = pack_half4(z0[0], z0[1], z0[2], z0[3]);
            uint2 u1 = pack_half4(z1[0], z1[1], z1[2], z1[3]);
            z4[j] = make_uint4(u0.x, u0.y, u1.x, u1.y);
            #pragma unroll
            for (int c = 0; c < 4; c++) {
                s[c] += z0[c] + z1[c];
                q[c] += z0[c]*z0[c] + z1[c]*z1[c];
            }
        }
        reduce_stats(s, q);
    }
    grid_barrier(&g_ebar_cnt, &g_ebar_rel, 1, EGRID,
                 (double)NE, p.mg1, p.mbe1, g_ma1, g_mb1);

    // ---- phase 2: stream z, layer-2 stats (2 edges/iter) ----
    {
        float a1[4], b1[4], W2[16], bb2[4];
        #pragma unroll
        for (int c = 0; c < 4; c++) { a1[c] = g_ma1[c]; b1[c] = g_mb1[c]; bb2[c] = __ldg(&p.mb2[c]); }
        #pragma unroll
        for (int k = 0; k < 16; k++) W2[k] = __ldg(&p.mW2[k]);

        float s[4] = {0,0,0,0}, q[4] = {0,0,0,0};
        const uint4* z4 = (const uint4*)g_z16;
        for (int j = tid; j < NE/2; j += ETHREADS) {
            uint4 u = __ldg(&z4[j]);
            float z0[4], z1[4];
            unpack_half4(u.x, u.y, z0);
            unpack_half4(u.z, u.w, z1);
            #pragma unroll
            for (int e = 0; e < 2; e++) {
                const float* z = (e == 0) ? z0 : z1;
                float y[4];
                #pragma unroll
                for (int c = 0; c < 4; c++) y[c] = fmaxf(0.f, z[c] * a1[c] + b1[c]);
                #pragma unroll
                for (int c = 0; c < 4; c++) {
                    float z2 = bb2[c] + y[0]*W2[c] + y[1]*W2[4+c] + y[2]*W2[8+c] + y[3]*W2[12+c];
                    s[c] += z2; q[c] += z2*z2;
                }
            }
        }
        reduce_stats(s, q);
    }
    grid_barrier(&g_ebar_cnt, &g_ebar_rel, 2, EGRID,
                 (double)NE, p.mg2, p.mbe2, g_ma2, g_mb2);

    // ---- phase 3: stream z + dst, message, scatter-add (2 edges/iter) ----
    {
        float a1[4], b1[4], a2[4], b2a[4], W2[16], bb2[4];
        #pragma unroll
        for (int c = 0; c < 4; c++) {
            a1[c] = g_ma1[c]; b1[c] = g_mb1[c];
            a2[c] = g_ma2[c]; b2a[c] = g_mb2[c];
            bb2[c] = __ldg(&p.mb2[c]);
        }
        #pragma unroll
        for (int k = 0; k < 16; k++) W2[k] = __ldg(&p.mW2[k]);

        const int2* dst2 = (const int2*)p.dst;
        const uint4* z4 = (const uint4*)g_z16;
        for (int j = tid; j < NE/2; j += ETHREADS) {
            int2 di = __ldg(&dst2[j]);
            uint4 u = __ldg(&z4[j]);
            float z0[4], z1[4];
            unpack_half4(u.x, u.y, z0);
            unpack_half4(u.z, u.w, z1);
            float m0[4], m1[4];
            #pragma unroll
            for (int e = 0; e < 2; e++) {
                const float* z = (e == 0) ? z0 : z1;
                float* m = (e == 0) ? m0 : m1;
                float y[4];
                #pragma unroll
                for (int c = 0; c < 4; c++) y[c] = fmaxf(0.f, z[c] * a1[c] + b1[c]);
                #pragma unroll
                for (int c = 0; c < 4; c++) {
                    float z2 = bb2[c] + y[0]*W2[c] + y[1]*W2[4+c] + y[2]*W2[8+c] + y[3]*W2[12+c];
                    m[c] = fmaxf(0.f, z2 * a2[c] + b2a[c]);
                }
            }
            float4* a0 = &g_aggr[di.x];
            float4* a1p = &g_aggr[di.y];
            asm volatile("red.global.add.v4.f32 [%0], {%1, %2, %3, %4};"
                         :: "l"(a0), "f"(m0[0]), "f"(m0[1]), "f"(m0[2]), "f"(m0[3]) : "memory");
            asm volatile("red.global.add.v4.f32 [%0], {%1, %2, %3, %4};"
                         :: "l"(a1p), "f"(m1[0]), "f"(m1[1]), "f"(m1[2]), "f"(m1[3]) : "memory");
        }
    }
}

// ======================= fused node-update kernel ===========================
// Each thread owns up to 2 nodes; zu/z2 stay in registers across phases.
__global__ void __launch_bounds__(UTB, 2) k_upd(P p) {
    const int tid = blockIdx.x * UTB + threadIdx.x;
    if (tid == 0) { g_ebar_cnt = 0; g_ebar_rel = 0; }  // reset edge barrier for next replay

    const int n0 = tid, n1 = tid + UTHREADS;
    const bool v0 = (n0 < NN), v1 = (n1 < NN);

    float x0[8], x1[8];
    if (v0) {
        float2 ps = __ldg((const float2*)&p.pos[2*n0]);
        float2 vl = __ldg((const float2*)&p.vel[2*n0]);
        float4 ag = g_aggr[n0];
        x0[0]=ps.x; x0[1]=ps.y; x0[2]=vl.x; x0[3]=vl.y;
        x0[4]=ag.x; x0[5]=ag.y; x0[6]=ag.z; x0[7]=ag.w;
    }
    if (v1) {
        float2 ps = __ldg((const float2*)&p.pos[2*n1]);
        float2 vl = __ldg((const float2*)&p.vel[2*n1]);
        float4 ag = g_aggr[n1];
        x1[0]=ps.x; x1[1]=ps.y; x1[2]=vl.x; x1[3]=vl.y;
        x1[4]=ag.x; x1[5]=ag.y; x1[6]=ag.z; x1[7]=ag.w;
    }

    // ---- phase 0: layer-1 pre-BN (registers) + stats ----
    float zu0[4], zu1[4];
    {
        float W[32], bb[4];
        #pragma unroll
        for (int k = 0; k < 32; k++) W[k] = __ldg(&p.uW1[k]);
        #pragma unroll
        for (int c = 0; c < 4; c++) bb[c] = __ldg(&p.ub1[c]);

        float s[4] = {0,0,0,0}, q[4] = {0,0,0,0};
        if (v0) {
            #pragma unroll
            for (int c = 0; c < 4; c++) {
                float acc = bb[c];
                #pragma unroll
                for (int k = 0; k < 8; k++) acc += x0[k] * W[k*4 + c];
                zu0[c] = acc; s[c] += acc; q[c] += acc*acc;
            }
        }
        if (v1) {
            #pragma unroll
            for (int c = 0; c < 4; c++) {
                float acc = bb[c];
                #pragma unroll
                for (int k = 0; k < 8; k++) acc += x1[k] * W[k*4 + c];
                zu1[c] = acc; s[c] += acc; q[c] += acc*acc;
            }
        }
        reduce_stats(s, q);
    }
    grid_barrier(&g_ubar_cnt, &g_ubar_rel, 0, UGRID,
                 (double)NN, p.ug1, p.ube1, g_ua1, g_ub1);

    // ---- phase 1: layer-2 pre-BN (registers) + stats ----
    float z20[4], z21[4];
    {
        float a1[4], b1[4], W2[16], bb2[4];
        #pragma unroll
        for (int c = 0; c < 4; c++) { a1[c] = g_ua1[c]; b1[c] = g_ub1[c]; bb2[c] = __ldg(&p.ub2[c]); }
        #pragma unroll
        for (int k = 0; k < 16; k++) W2[k] = __ldg(&p.uW2[k]);

        float s[4] = {0,0,0,0}, q[4] = {0,0,0,0};
        if (v0) {
            float y[4];
            #pragma unroll
            for (int c = 0; c < 4; c++) y[c] = fmaxf(0.f, zu0[c] * a1[c] + b1[c]);
            #pragma unroll
            for (int c = 0; c < 4; c++) {
                z20[c] = bb2[c] + y[0]*W2[c] + y[1]*W2[4+c] + y[2]*W2[8+c] + y[3]*W2[12+c];
                s[c] += z20[c]; q[c] += z20[c]*z20[c];
            }
        }
        if (v1) {
            float y[4];
            #pragma unroll
            for (int c = 0; c < 4; c++) y[c] = fmaxf(0.f, zu1[c] * a1[c] + b1[c]);
            #pragma unroll
            for (int c = 0; c < 4; c++) {
                z21[c] = bb2[c] + y[0]*W2[c] + y[1]*W2[4+c] + y[2]*W2[8+c] + y[3]*W2[12+c];
                s[c] += z21[c]; q[c] += z21[c]*z21[c];
            }
        }
        reduce_stats(s, q);
    }
    grid_barrier(&g_ubar_cnt, &g_ubar_rel, 1, UGRID,
                 (double)NN, p.ug2, p.ube2, g_ua2, g_ub2);

    // ---- phase 2: final BN+ReLU + prediction head ----
    {
        float a2[4], b2[4], pW[8], pb0, pb1;
        #pragma unroll
        for (int c = 0; c < 4; c++) { a2[c] = g_ua2[c]; b2[c] = g_ub2[c]; }
        #pragma unroll
        for (int k = 0; k < 8; k++) pW[k] = __ldg(&p.pW[k]);
        pb0 = __ldg(&p.pb[0]); pb1 = __ldg(&p.pb[1]);

        if (v0) {
            float u[4];
            #pragma unroll
            for (int c = 0; c < 4; c++) u[c] = fmaxf(0.f, z20[c] * a2[c] + b2[c]);
            float o0 = pb0, o1 = pb1;
            #pragma unroll
            for (int k = 0; k < 4; k++) { o0 += u[k]*pW[k*2]; o1 += u[k]*pW[k*2+1]; }
            ((float2*)p.out)[n0] = make_float2(o0, o1);
        }
        if (v1) {
            float u[4];
            #pragma unroll
            for (int c = 0; c < 4; c++) u[c] = fmaxf(0.f, z21[c] * a2[c] + b2[c]);
            float o0 = pb0, o1 = pb1;
            #pragma unroll
            for (int k = 0; k < 4; k++) { o0 += u[k]*pW[k*2]; o1 += u[k]*pW[k*2+1]; }
            ((float2*)p.out)[n1] = make_float2(o0, o1);
        }
    }
}

// ---------------- launch -----------------------------------------------------
extern "C" void kernel_launch(void* const* d_in, const int* in_sizes, int n_in,
                              void* d_out, int out_size) {
    P p;
    p.pos = (const float*)d_in[0];
    p.vel = (const float*)d_in[1];
    const int* ei = (const int*)d_in[2];   // int32 (JAX canonicalizes int64 -> int32)
    p.src = ei;            // edge_index[0]
    p.dst = ei + NE;       // edge_index[1]
    p.mW1  = (const float*)d_in[3];  p.mb1  = (const float*)d_in[4];
    p.mg1  = (const float*)d_in[5];  p.mbe1 = (const float*)d_in[6];
    p.mW2  = (const float*)d_in[7];  p.mb2  = (const float*)d_in[8];
    p.mg2  = (const float*)d_in[9];  p.mbe2 = (const float*)d_in[10];
    p.uW1  = (const float*)d_in[11]; p.ub1  = (const float*)d_in[12];
    p.ug1  = (const float*)d_in[13]; p.ube1 = (const float*)d_in[14];
    p.uW2  = (const float*)d_in[15]; p.ub2  = (const float*)d_in[16];
    p.ug2  = (const float*)d_in[17]; p.ube2 = (const float*)d_in[18];
    p.pW   = (const float*)d_in[19]; p.pb   = (const float*)d_in[20];
    p.out  = (float*)d_out;

    k_edge<<<EGRID, ETB>>>(p);
    k_upd <<<UGRID, UTB>>>(p);
}

// round 14
// speedup vs baseline: 1.0576x; 1.0037x over previous
#include <cuda_runtime.h>
#include <cuda_bf16.h>
#include <cuda_fp16.h>

#define NN 100000
#define NE 6400000
#define EGRID 592
#define ETB 256
#define ETHREADS (EGRID * ETB)   // 151552, = 148 SMs x 4 blocks
#define UGRID 296
#define UTB 256
#define UTHREADS (UGRID * UTB)   // 75776,  = 148 SMs x 2 blocks
static constexpr float BN_EPS = 1e-5f;

// ---------------- scratch (static device arrays; no runtime alloc) ---------
__device__ float4 g_A[NN];            // h @ msg_W1[0:4]   (dst-side partial)
__device__ float4 g_B[NN];            // h @ msg_W1[4:8]+b (src-side partial)
__device__ uint2  g_z16[NE];          // per-edge layer-1 pre-BN, packed half4 (51.2 MB)
__device__ float4 g_aggr[NN];         // scatter-add target

__device__ double g_sum[4];
__device__ double g_sq[4];

// grid-barrier state (monotonic counters; each kernel resets the OTHER's)
__device__ unsigned          g_ebar_cnt;
__device__ volatile unsigned g_ebar_rel;
__device__ unsigned          g_ubar_cnt;
__device__ volatile unsigned g_ubar_rel;

__device__ float g_ma1[4], g_mb1[4];  // msg BN1 affine
__device__ float g_ma2[4], g_mb2[4];  // msg BN2 affine
__device__ float g_ua1[4], g_ub1[4];  // upd BN1 affine
__device__ float g_ua2[4], g_ub2[4];  // upd BN2 affine

struct P {
    const float* pos; const float* vel;
    const int* src; const int* dst;   // edge_index rows (int32)
    const float *mW1,*mb1,*mg1,*mbe1,*mW2,*mb2,*mg2,*mbe2;
    const float *uW1,*ub1,*ug1,*ube1,*uW2,*ub2,*ug2,*ube2;
    const float *pW,*pb;
    float* out;
};

// ---------------- half4 pack/unpack -----------------------------------------
__device__ __forceinline__ uint2 pack_half4(float x, float y, float z, float w) {
    __half2 a = __floats2half2_rn(x, y);
    __half2 b = __floats2half2_rn(z, w);
    uint2 u;
    u.x = *reinterpret_cast<unsigned*>(&a);
    u.y = *reinterpret_cast<unsigned*>(&b);
    return u;
}
__device__ __forceinline__ void unpack_half4(unsigned lo, unsigned hi, float z[4]) {
    __half2 a = *reinterpret_cast<__half2*>(&lo);
    __half2 b = *reinterpret_cast<__half2*>(&hi);
    float2 f0 = __half22float2(a), f1 = __half22float2(b);
    z[0] = f0.x; z[1] = f0.y; z[2] = f1.x; z[3] = f1.y;
}

// ---------------- block-level stats reduce -> global atomics ----------------
__device__ __forceinline__ void reduce_stats(float s[4], float q[4]) {
    #pragma unroll
    for (int o = 16; o > 0; o >>= 1) {
        #pragma unroll
        for (int c = 0; c < 4; c++) {
            s[c] += __shfl_down_sync(0xffffffffu, s[c], o);
            q[c] += __shfl_down_sync(0xffffffffu, q[c], o);
        }
    }
    __shared__ float shs[4][8], shq[4][8];
    int w = threadIdx.x >> 5;
    if ((threadIdx.x & 31) == 0) {
        #pragma unroll
        for (int c = 0; c < 4; c++) { shs[c][w] = s[c]; shq[c][w] = q[c]; }
    }
    __syncthreads();
    if (threadIdx.x == 0) {
        int nw = blockDim.x >> 5;
        #pragma unroll
        for (int c = 0; c < 4; c++) {
            double ts = 0.0, tq = 0.0;
            for (int i = 0; i < nw; i++) { ts += (double)shs[c][i]; tq += (double)shq[c][i]; }
            atomicAdd(&g_sum[c], ts);
            atomicAdd(&g_sq[c],  tq);
        }
    }
}

// finalize BN affine from global moments (VOLATILE reads: L1 may hold stale
// lines from a previous finalize within this same launch; atomics only hit L2)
__device__ __forceinline__ void bn_finalize(double count, const float* gamma, const float* beta,
                                            float* aout, float* bout) {
    #pragma unroll
    for (int c = 0; c < 4; c++) {
        double m = ((volatile double*)g_sum)[c] / count;
        double v = ((volatile double*)g_sq)[c] / count - m * m;
        float  al = __ldg(&gamma[c]) * rsqrtf((float)v + BN_EPS);
        aout[c] = al;
        bout[c] = __ldg(&beta[c]) - (float)m * al;
        g_sum[c] = 0.0; g_sq[c] = 0.0;
    }
}

// grid-wide barrier; last arriver optionally runs the BN finalize before release.
// Requires ALL blocks of the grid co-resident (grid == exact SM capacity).
__device__ __forceinline__ void grid_barrier(unsigned* cnt, volatile unsigned* rel,
                                             int phase, int grid,
                                             double count = 0.0,
                                             const float* gamma = nullptr,
                                             const float* beta  = nullptr,
                                             float* aout = nullptr, float* bout = nullptr) {
    __threadfence();
    __syncthreads();
    if (threadIdx.x == 0) {
        unsigned old = atomicAdd(cnt, 1u);
        if (old == (unsigned)(phase * grid + grid - 1)) {
            if (gamma) bn_finalize(count, gamma, beta, aout, bout);
            __threadfence();
            *rel = (unsigned)(phase + 1);
        } else {
            while (*rel <= (unsigned)phase) __nanosleep(64);
        }
        __threadfence();
    }
    __syncthreads();
}

// ======================= fused edge kernel ==================================
// phase0: node precompute   -> barrier
// phase1: gather+store z, BN1 stats -> barrier(+fin BN1)
// phase2: stream z, BN2 stats       -> barrier(+fin BN2)
// phase3: stream z+dst (evict-first: last use), message, scatter-add
__global__ void __launch_bounds__(ETB, 4) k_edge(P p) {
    const int tid = blockIdx.x * ETB + threadIdx.x;

    // ---- phase 0: per-node precompute + state reset ----
    if (tid == 0) {
        g_ubar_cnt = 0; g_ubar_rel = 0;   // reset k_upd's barrier for this replay
        #pragma unroll
        for (int c = 0; c < 4; c++) { g_sum[c] = 0.0; g_sq[c] = 0.0; }
    }
    if (tid < NN) {
        float h0 = __ldg(&p.pos[2*tid]),  h1 = __ldg(&p.pos[2*tid+1]);
        float h2 = __ldg(&p.vel[2*tid]),  h3 = __ldg(&p.vel[2*tid+1]);
        float A[4], B[4];
        #pragma unroll
        for (int c = 0; c < 4; c++) {
            A[c] = h0*__ldg(&p.mW1[ 0+c]) + h1*__ldg(&p.mW1[ 4+c])
                 + h2*__ldg(&p.mW1[ 8+c]) + h3*__ldg(&p.mW1[12+c]);
            B[c] = __ldg(&p.mb1[c])
                 + h0*__ldg(&p.mW1[16+c]) + h1*__ldg(&p.mW1[20+c])
                 + h2*__ldg(&p.mW1[24+c]) + h3*__ldg(&p.mW1[28+c]);
        }
        g_A[tid]    = make_float4(A[0], A[1], A[2], A[3]);
        g_B[tid]    = make_float4(B[0], B[1], B[2], B[3]);
        g_aggr[tid] = make_float4(0.f, 0.f, 0.f, 0.f);
    }
    grid_barrier(&g_ebar_cnt, &g_ebar_rel, 0, EGRID);

    // ---- phase 1: gather once, pack-store z, layer-1 stats (2 edges/iter) ----
    {
        float s[4] = {0,0,0,0}, q[4] = {0,0,0,0};
        const int2* src2 = (const int2*)p.src;
        const int2* dst2 = (const int2*)p.dst;
        uint4* z4 = (uint4*)g_z16;
        for (int j = tid; j < NE/2; j += ETHREADS) {
            int2 si = __ldg(&src2[j]);
            int2 di = __ldg(&dst2[j]);
            float4 A0 = g_A[di.x], B0 = g_B[si.x];
            float4 A1 = g_A[di.y], B1 = g_B[si.y];
            float z0[4] = {A0.x+B0.x, A0.y+B0.y, A0.z+B0.z, A0.w+B0.w};
            float z1[4] = {A1.x+B1.x, A1.y+B1.y, A1.z+B1.z, A1.w+B1.w};
            uint2 u0 = pack_half4(z0[0], z0[1], z0[2], z0[3]);
            uint2 u1 = pack_half4(z1[0], z1[1], z1[2], z1[3]);
            z4[j] = make_uint4(u0.x, u0.y, u1.x, u1.y);
            #pragma unroll
            for (int c = 0; c < 4; c++) {
                s[c] += z0[c] + z1[c];
                q[c] += z0[c]*z0[c] + z1[c]*z1[c];
            }
        }
        reduce_stats(s, q);
    }
    grid_barrier(&g_ebar_cnt, &g_ebar_rel, 1, EGRID,
                 (double)NE, p.mg1, p.mbe1, g_ma1, g_mb1);

    // ---- phase 2: stream z, layer-2 stats (2 edges/iter) ----
    // default cache policy: z lines stay L2-resident for phase 3's re-read
    {
        float a1[4], b1[4], W2[16], bb2[4];
        #pragma unroll
        for (int c = 0; c < 4; c++) { a1[c] = g_ma1[c]; b1[c] = g_mb1[c]; bb2[c] = __ldg(&p.mb2[c]); }
        #pragma unroll
        for (int k = 0; k < 16; k++) W2[k] = __ldg(&p.mW2[k]);

        float s[4] = {0,0,0,0}, q[4] = {0,0,0,0};
        const uint4* z4 = (const uint4*)g_z16;
        for (int j = tid; j < NE/2; j += ETHREADS) {
            uint4 u = __ldg(&z4[j]);
            float z0[4], z1[4];
            unpack_half4(u.x, u.y, z0);
            unpack_half4(u.z, u.w, z1);
            #pragma unroll
            for (int e = 0; e < 2; e++) {
                const float* z = (e == 0) ? z0 : z1;
                float y[4];
                #pragma unroll
                for (int c = 0; c < 4; c++) y[c] = fmaxf(0.f, z[c] * a1[c] + b1[c]);
                #pragma unroll
                for (int c = 0; c < 4; c++) {
                    float z2 = bb2[c] + y[0]*W2[c] + y[1]*W2[4+c] + y[2]*W2[8+c] + y[3]*W2[12+c];
                    s[c] += z2; q[c] += z2*z2;
                }
            }
        }
        reduce_stats(s, q);
    }
    grid_barrier(&g_ebar_cnt, &g_ebar_rel, 2, EGRID,
                 (double)NE, p.mg2, p.mbe2, g_ma2, g_mb2);

    // ---- phase 3: stream z + dst (LAST USE -> evict-first), message,
    //      scatter-add (2 edges/iter) ----
    {
        float a1[4], b1[4], a2[4], b2a[4], W2[16], bb2[4];
        #pragma unroll
        for (int c = 0; c < 4; c++) {
            a1[c] = g_ma1[c]; b1[c] = g_mb1[c];
            a2[c] = g_ma2[c]; b2a[c] = g_mb2[c];
            bb2[c] = __ldg(&p.mb2[c]);
        }
        #pragma unroll
        for (int k = 0; k < 16; k++) W2[k] = __ldg(&p.mW2[k]);

        const int2* dst2 = (const int2*)p.dst;
        const uint4* z4 = (const uint4*)g_z16;
        for (int j = tid; j < NE/2; j += ETHREADS) {
            int2 di = __ldcs(&dst2[j]);        // last use: evict-first
            uint4 u = __ldcs(&z4[j]);          // last use: evict-first
            float z0[4], z1[4];
            unpack_half4(u.x, u.y, z0);
            unpack_half4(u.z, u.w, z1);
            float m0[4], m1[4];
            #pragma unroll
            for (int e = 0; e < 2; e++) {
                const float* z = (e == 0) ? z0 : z1;
                float* m = (e == 0) ? m0 : m1;
                float y[4];
                #pragma unroll
                for (int c = 0; c < 4; c++) y[c] = fmaxf(0.f, z[c] * a1[c] + b1[c]);
                #pragma unroll
                for (int c = 0; c < 4; c++) {
                    float z2 = bb2[c] + y[0]*W2[c] + y[1]*W2[4+c] + y[2]*W2[8+c] + y[3]*W2[12+c];
                    m[c] = fmaxf(0.f, z2 * a2[c] + b2a[c]);
                }
            }
            float4* a0 = &g_aggr[di.x];
            float4* a1p = &g_aggr[di.y];
            asm volatile("red.global.add.v4.f32 [%0], {%1, %2, %3, %4};"
                         :: "l"(a0), "f"(m0[0]), "f"(m0[1]), "f"(m0[2]), "f"(m0[3]) : "memory");
            asm volatile("red.global.add.v4.f32 [%0], {%1, %2, %3, %4};"
                         :: "l"(a1p), "f"(m1[0]), "f"(m1[1]), "f"(m1[2]), "f"(m1[3]) : "memory");
        }
    }
}

// ======================= fused node-update kernel ===========================
// Each thread owns up to 2 nodes; zu/z2 stay in registers across phases.
__global__ void __launch_bounds__(UTB, 2) k_upd(P p) {
    const int tid = blockIdx.x * UTB + threadIdx.x;
    if (tid == 0) { g_ebar_cnt = 0; g_ebar_rel = 0; }  // reset edge barrier for next replay

    const int n0 = tid, n1 = tid + UTHREADS;
    const bool v0 = (n0 < NN), v1 = (n1 < NN);

    float x0[8], x1[8];
    if (v0) {
        float2 ps = __ldg((const float2*)&p.pos[2*n0]);
        float2 vl = __ldg((const float2*)&p.vel[2*n0]);
        float4 ag = g_aggr[n0];
        x0[0]=ps.x; x0[1]=ps.y; x0[2]=vl.x; x0[3]=vl.y;
        x0[4]=ag.x; x0[5]=ag.y; x0[6]=ag.z; x0[7]=ag.w;
    }
    if (v1) {
        float2 ps = __ldg((const float2*)&p.pos[2*n1]);
        float2 vl = __ldg((const float2*)&p.vel[2*n1]);
        float4 ag = g_aggr[n1];
        x1[0]=ps.x; x1[1]=ps.y; x1[2]=vl.x; x1[3]=vl.y;
        x1[4]=ag.x; x1[5]=ag.y; x1[6]=ag.z; x1[7]=ag.w;
    }

    // ---- phase 0: layer-1 pre-BN (registers) + stats ----
    float zu0[4], zu1[4];
    {
        float W[32], bb[4];
        #pragma unroll
        for (int k = 0; k < 32; k++) W[k] = __ldg(&p.uW1[k]);
        #pragma unroll
        for (int c = 0; c < 4; c++) bb[c] = __ldg(&p.ub1[c]);

        float s[4] = {0,0,0,0}, q[4] = {0,0,0,0};
        if (v0) {
            #pragma unroll
            for (int c = 0; c < 4; c++) {
                float acc = bb[c];
                #pragma unroll
                for (int k = 0; k < 8; k++) acc += x0[k] * W[k*4 + c];
                zu0[c] = acc; s[c] += acc; q[c] += acc*acc;
            }
        }
        if (v1) {
            #pragma unroll
            for (int c = 0; c < 4; c++) {
                float acc = bb[c];
                #pragma unroll
                for (int k = 0; k < 8; k++) acc += x1[k] * W[k*4 + c];
                zu1[c] = acc; s[c] += acc; q[c] += acc*acc;
            }
        }
        reduce_stats(s, q);
    }
    grid_barrier(&g_ubar_cnt, &g_ubar_rel, 0, UGRID,
                 (double)NN, p.ug1, p.ube1, g_ua1, g_ub1);

    // ---- phase 1: layer-2 pre-BN (registers) + stats ----
    float z20[4], z21[4];
    {
        float a1[4], b1[4], W2[16], bb2[4];
        #pragma unroll
        for (int c = 0; c < 4; c++) { a1[c] = g_ua1[c]; b1[c] = g_ub1[c]; bb2[c] = __ldg(&p.ub2[c]); }
        #pragma unroll
        for (int k = 0; k < 16; k++) W2[k] = __ldg(&p.uW2[k]);

        float s[4] = {0,0,0,0}, q[4] = {0,0,0,0};
        if (v0) {
            float y[4];
            #pragma unroll
            for (int c = 0; c < 4; c++) y[c] = fmaxf(0.f, zu0[c] * a1[c] + b1[c]);
            #pragma unroll
            for (int c = 0; c < 4; c++) {
                z20[c] = bb2[c] + y[0]*W2[c] + y[1]*W2[4+c] + y[2]*W2[8+c] + y[3]*W2[12+c];
                s[c] += z20[c]; q[c] += z20[c]*z20[c];
            }
        }
        if (v1) {
            float y[4];
            #pragma unroll
            for (int c = 0; c < 4; c++) y[c] = fmaxf(0.f, zu1[c] * a1[c] + b1[c]);
            #pragma unroll
            for (int c = 0; c < 4; c++) {
                z21[c] = bb2[c] + y[0]*W2[c] + y[1]*W2[4+c] + y[2]*W2[8+c] + y[3]*W2[12+c];
                s[c] += z21[c]; q[c] += z21[c]*z21[c];
            }
        }
        reduce_stats(s, q);
    }
    grid_barrier(&g_ubar_cnt, &g_ubar_rel, 1, UGRID,
                 (double)NN, p.ug2, p.ube2, g_ua2, g_ub2);

    // ---- phase 2: final BN+ReLU + prediction head ----
    {
        float a2[4], b2[4], pW[8], pb0, pb1;
        #pragma unroll
        for (int c = 0; c < 4; c++) { a2[c] = g_ua2[c]; b2[c] = g_ub2[c]; }
        #pragma unroll
        for (int k = 0; k < 8; k++) pW[k] = __ldg(&p.pW[k]);
        pb0 = __ldg(&p.pb[0]); pb1 = __ldg(&p.pb[1]);

        if (v0) {
            float u[4];
            #pragma unroll
            for (int c = 0; c < 4; c++) u[c] = fmaxf(0.f, z20[c] * a2[c] + b2[c]);
            float o0 = pb0, o1 = pb1;
            #pragma unroll
            for (int k = 0; k < 4; k++) { o0 += u[k]*pW[k*2]; o1 += u[k]*pW[k*2+1]; }
            ((float2*)p.out)[n0] = make_float2(o0, o1);
        }
        if (v1) {
            float u[4];
            #pragma unroll
            for (int c = 0; c < 4; c++) u[c] = fmaxf(0.f, z21[c] * a2[c] + b2[c]);
            float o0 = pb0, o1 = pb1;
            #pragma unroll
            for (int k = 0; k < 4; k++) { o0 += u[k]*pW[k*2]; o1 += u[k]*pW[k*2+1]; }
            ((float2*)p.out)[n1] = make_float2(o0, o1);
        }
    }
}

// ---------------- launch -----------------------------------------------------
extern "C" void kernel_launch(void* const* d_in, const int* in_sizes, int n_in,
                              void* d_out, int out_size) {
    P p;
    p.pos = (const float*)d_in[0];
    p.vel = (const float*)d_in[1];
    const int* ei = (const int*)d_in[2];   // int32 (JAX canonicalizes int64 -> int32)
    p.src = ei;            // edge_index[0]
    p.dst = ei + NE;       // edge_index[1]
    p.mW1  = (const float*)d_in[3];  p.mb1  = (const float*)d_in[4];
    p.mg1  = (const float*)d_in[5];  p.mbe1 = (const float*)d_in[6];
    p.mW2  = (const float*)d_in[7];  p.mb2  = (const float*)d_in[8];
    p.mg2  = (const float*)d_in[9];  p.mbe2 = (const float*)d_in[10];
    p.uW1  = (const float*)d_in[11]; p.ub1  = (const float*)d_in[12];
    p.ug1  = (const float*)d_in[13]; p.ube1 = (const float*)d_in[14];
    p.uW2  = (const float*)d_in[15]; p.ub2  = (const float*)d_in[16];
    p.ug2  = (const float*)d_in[17]; p.ube2 = (const float*)d_in[18];
    p.pW   = (const float*)d_in[19]; p.pb   = (const float*)d_in[20];
    p.out  = (float*)d_out;

    k_edge<<<EGRID, ETB>>>(p);
    k_upd <<<UGRID, UTB>>>(p);
}